// round 1
// baseline (speedup 1.0000x reference)
#include <cuda_runtime.h>
#include <math.h>

#define NBATCH 8192
#define NS 16
#define DIM 256
#define NH 8
#define HD 32
#define PF 48
#define NROWS (NBATCH*NS)   /* 131072 */
#define EPSC 1e-5f
#define ATT_SCALE 0.17677669529663687f  /* 32^-0.5 */
#define QS 770              /* padded qkv smem row stride (770%32==2 -> conflict-free n access) */

/* ---------------- device scratch (no allocations allowed) ---------------- */
__device__ float g_part_S[256][PF*PF];
__device__ float g_part_m[256][PF];
__device__ float g_S[PF*PF];
__device__ float g_m[PF];                 /* mean of pos */
__device__ float g_w1T[3][PF][DIM];       /* BN-folded layer-1 weight, transposed */
__device__ float g_b1e[3][DIM];           /* BN-folded layer-1 bias */
__device__ float g_qkvT[DIM][3*DIM];
__device__ float g_w2T[3][DIM][DIM];
__device__ float g_projT[DIM][DIM];
__device__ float g_pos[3][NROWS][DIM];    /* pos_q / pos_k / pos_v (~402 MB) */

/* ---------------- 1) partial stats: sum(pos), sum(pos pos^T) ---------------- */
__global__ void k_stats_part(const float* __restrict__ pr) {
    __shared__ float ps[64*PF];
    int tid = threadIdx.x;
    int ti = tid >> 4, tj = tid & 15;     /* 16x16 thread grid, 3x3 tiles -> 48x48 */
    float acc[9];
    float asum[3];
#pragma unroll
    for (int i = 0; i < 9; i++) acc[i] = 0.f;
    asum[0] = asum[1] = asum[2] = 0.f;
    int r0 = blockIdx.x * 512;
    for (int t = 0; t < 8; t++) {
        const float* src = pr + (long)(r0 + t*64) * PF;
        for (int i = tid; i < 64*PF; i += 256) ps[i] = src[i];
        __syncthreads();
        for (int r = 0; r < 64; r++) {
            float si0 = ps[r*PF + 3*ti + 0];
            float si1 = ps[r*PF + 3*ti + 1];
            float si2 = ps[r*PF + 3*ti + 2];
            float sj0 = ps[r*PF + 3*tj + 0];
            float sj1 = ps[r*PF + 3*tj + 1];
            float sj2 = ps[r*PF + 3*tj + 2];
            acc[0] += si0*sj0; acc[1] += si0*sj1; acc[2] += si0*sj2;
            acc[3] += si1*sj0; acc[4] += si1*sj1; acc[5] += si1*sj2;
            acc[6] += si2*sj0; acc[7] += si2*sj1; acc[8] += si2*sj2;
            if (tj == 0) { asum[0] += si0; asum[1] += si1; asum[2] += si2; }
        }
        __syncthreads();
    }
#pragma unroll
    for (int a = 0; a < 3; a++)
#pragma unroll
        for (int bq = 0; bq < 3; bq++)
            g_part_S[blockIdx.x][(3*ti + a)*PF + 3*tj + bq] = acc[a*3 + bq];
    if (tj == 0) {
        g_part_m[blockIdx.x][3*ti + 0] = asum[0];
        g_part_m[blockIdx.x][3*ti + 1] = asum[1];
        g_part_m[blockIdx.x][3*ti + 2] = asum[2];
    }
}

/* ---------------- 2) deterministic final reduce ---------------- */
__global__ void k_stats_red() {
    int i = blockIdx.x * 256 + threadIdx.x;
    if (i < PF*PF) {
        float s = 0.f;
        for (int c = 0; c < 256; c++) s += g_part_S[c][i];
        g_S[i] = s;
    } else if (i < PF*PF + PF) {
        int j = i - PF*PF;
        float s = 0.f;
        for (int c = 0; c < 256; c++) s += g_part_m[c][j];
        g_m[j] = s * (1.f / (float)NROWS);
    }
}

/* ---------------- 3) transpose big weights for coalesced reads ---------------- */
__global__ void k_prep(const float* __restrict__ qkvw, const float* __restrict__ w2q,
                       const float* __restrict__ w2k, const float* __restrict__ w2v,
                       const float* __restrict__ projw) {
    int idx = blockIdx.x * blockDim.x + threadIdx.x;
    const int T0 = 768*256;
    const int T1 = T0 + 3*256*256;
    const int TT = T1 + 256*256;
    for (; idx < TT; idx += gridDim.x * blockDim.x) {
        if (idx < T0) {
            int d = idx / 768, c = idx % 768;
            g_qkvT[d][c] = qkvw[c*256 + d];
        } else if (idx < T1) {
            int l = idx - T0;
            int p = l >> 16; l &= 65535;
            int d = l >> 8, c = l & 255;
            const float* w = (p == 0 ? w2q : (p == 1 ? w2k : w2v));
            g_w2T[p][d][c] = w[c*256 + d];
        } else {
            int l = idx - T1;
            int d = l >> 8, c = l & 255;
            g_projT[d][c] = projw[c*256 + d];
        }
    }
}

/* ---------------- 4) fold BatchNorm into layer-1 affine (1 warp / channel) ---------------- */
__global__ void k_fold(const float* __restrict__ qw1, const float* __restrict__ qb1,
                       const float* __restrict__ qg,  const float* __restrict__ qbe,
                       const float* __restrict__ kw1, const float* __restrict__ kb1,
                       const float* __restrict__ kg,  const float* __restrict__ kbe,
                       const float* __restrict__ vw1, const float* __restrict__ vb1,
                       const float* __restrict__ vg,  const float* __restrict__ vbe) {
    __shared__ float ws[8][PF];
    int tid = threadIdx.x;
    int wl = tid >> 5, lane = tid & 31;
    int ch = blockIdx.x * 8 + wl;         /* 0..767 */
    int p = ch >> 8, c = ch & 255;
    const float* w1 = (p == 0 ? qw1 : (p == 1 ? kw1 : vw1)) + c*PF;
    const float* b1 = (p == 0 ? qb1 : (p == 1 ? kb1 : vb1));
    const float* gg = (p == 0 ? qg  : (p == 1 ? kg  : vg ));
    const float* be = (p == 0 ? qbe : (p == 1 ? kbe : vbe));
    ws[wl][lane] = w1[lane];
    if (lane < PF - 32) ws[wl][lane + 32] = w1[lane + 32];
    __syncwarp();
    float quad = 0.f, wm = 0.f;
#pragma unroll
    for (int ii = 0; ii < 2; ii++) {
        int i = lane + ii*32;
        if (i < PF) {
            float wi = ws[wl][i];
            float t = 0.f;
            for (int j = 0; j < PF; j++) t += g_S[i*PF + j] * ws[wl][j];
            quad += wi * t;
            wm   += wi * g_m[i];
        }
    }
    for (int off = 16; off > 0; off >>= 1) {
        quad += __shfl_xor_sync(0xffffffffu, quad, off);
        wm   += __shfl_xor_sync(0xffffffffu, wm,   off);
    }
    /* var = w^T (S/N - m m^T) w  = quad/N - (w.m)^2 */
    float var   = quad * (1.f / (float)NROWS) - wm * wm;
    float scale = gg[c] * rsqrtf(var + EPSC);
    float mu    = wm + b1[c];
    float b1e   = (b1[c] - mu) * scale + be[c];
#pragma unroll
    for (int ii = 0; ii < 2; ii++) {
        int j = lane + ii*32;
        if (j < PF) g_w1T[p][j][c] = ws[wl][j] * scale;
    }
    if (lane == 0) g_b1e[p][c] = b1e;
}

/* ---------------- 5) pos MLPs: relu(pos@W1eff.T+b1eff)@w2.T+b2 -> g_pos ---------------- */
__global__ void __launch_bounds__(256, 2) k_posmlp(const float* __restrict__ pr,
        const float* __restrict__ qb2, const float* __restrict__ kb2,
        const float* __restrict__ vb2) {
    extern __shared__ float smdyn[];
    float* ps = smdyn;                 /* 64*48 */
    float* hs = smdyn + 64*PF;         /* 64*256 */
    int tid = threadIdx.x;
    int r0 = blockIdx.x * 64;
    for (int i = tid; i < 64*PF; i += 256) ps[i] = pr[(long)r0*PF + i];
    __syncthreads();
    int c0 = (tid & 31) * 8;
    int rr = (tid >> 5) * 8;
    for (int p = 0; p < 3; p++) {
        float acc[8][8];
#pragma unroll
        for (int a = 0; a < 8; a++)
#pragma unroll
            for (int bq = 0; bq < 8; bq++) acc[a][bq] = 0.f;
        const float* w1T = &g_w1T[p][0][0];
        for (int j = 0; j < PF; j++) {
            float4 wa = *(const float4*)(w1T + j*DIM + c0);
            float4 wb = *(const float4*)(w1T + j*DIM + c0 + 4);
            float w[8] = {wa.x, wa.y, wa.z, wa.w, wb.x, wb.y, wb.z, wb.w};
#pragma unroll
            for (int ri = 0; ri < 8; ri++) {
                float pv = ps[(rr + ri)*PF + j];
#pragma unroll
                for (int ci = 0; ci < 8; ci++) acc[ri][ci] += pv * w[ci];
            }
        }
        {
            float4 ba = *(const float4*)(&g_b1e[p][c0]);
            float4 bb = *(const float4*)(&g_b1e[p][c0 + 4]);
            float bi[8] = {ba.x, ba.y, ba.z, ba.w, bb.x, bb.y, bb.z, bb.w};
#pragma unroll
            for (int ri = 0; ri < 8; ri++)
#pragma unroll
                for (int ci = 0; ci < 8; ci++)
                    hs[(rr + ri)*DIM + c0 + ci] = fmaxf(acc[ri][ci] + bi[ci], 0.f);
        }
        __syncthreads();
#pragma unroll
        for (int a = 0; a < 8; a++)
#pragma unroll
            for (int bq = 0; bq < 8; bq++) acc[a][bq] = 0.f;
        const float* w2T = &g_w2T[p][0][0];
        for (int j = 0; j < DIM; j++) {
            float4 wa = *(const float4*)(w2T + j*DIM + c0);
            float4 wb = *(const float4*)(w2T + j*DIM + c0 + 4);
            float w[8] = {wa.x, wa.y, wa.z, wa.w, wb.x, wb.y, wb.z, wb.w};
#pragma unroll
            for (int ri = 0; ri < 8; ri++) {
                float hv = hs[(rr + ri)*DIM + j];
#pragma unroll
                for (int ci = 0; ci < 8; ci++) acc[ri][ci] += hv * w[ci];
            }
        }
        {
            const float* b2 = (p == 0 ? qb2 : (p == 1 ? kb2 : vb2));
            float4 ba = *(const float4*)(b2 + c0);
            float4 bb = *(const float4*)(b2 + c0 + 4);
            float bo[8] = {ba.x, ba.y, ba.z, ba.w, bb.x, bb.y, bb.z, bb.w};
#pragma unroll
            for (int ri = 0; ri < 8; ri++) {
                float4 o0 = make_float4(acc[ri][0] + bo[0], acc[ri][1] + bo[1],
                                        acc[ri][2] + bo[2], acc[ri][3] + bo[3]);
                float4 o1 = make_float4(acc[ri][4] + bo[4], acc[ri][5] + bo[5],
                                        acc[ri][6] + bo[6], acc[ri][7] + bo[7]);
                *(float4*)(&g_pos[p][r0 + rr + ri][c0])     = o0;
                *(float4*)(&g_pos[p][r0 + rr + ri][c0 + 4]) = o1;
            }
        }
        __syncthreads();
    }
}

/* ---------------- 6) main: qkv GEMM + attention + proj (1 CTA / batch) ---------------- */
__global__ void __launch_bounds__(256, 2) k_main(const float* __restrict__ x,
        const float* __restrict__ projb, float* __restrict__ out) {
    extern __shared__ float smdyn[];
    float* xs   = smdyn;               /* 16*256 : x, later reused for pre-proj out */
    float* qkvs = smdyn + 4096;        /* 16*QS  */
    float* wbuf = qkvs + 16*QS;        /* 8 warps * 1024 : (k+pos_q | pos_k), later (v+pos_v) */
    float* ats  = wbuf + 8*1024;       /* 8 * 16*17 attn */
    int tid = threadIdx.x;
    int b = blockIdx.x;
    const float* xb = x + (long)b * NS * DIM;
    for (int i = tid; i < NS*DIM; i += 256) xs[i] = xb[i];
    __syncthreads();
    /* --- qkv = x @ qkv_w.T : each thread owns 3 output columns for all 16 rows --- */
    {
        float a0[16], a1[16], a2[16];
#pragma unroll
        for (int r = 0; r < 16; r++) { a0[r] = 0.f; a1[r] = 0.f; a2[r] = 0.f; }
        const float* wt = &g_qkvT[0][0];
        for (int d = 0; d < DIM; d++) {
            float w0  = wt[d*768 + tid];
            float w1v = wt[d*768 + tid + 256];
            float w2v = wt[d*768 + tid + 512];
#pragma unroll
            for (int r = 0; r < 16; r++) {
                float xv = xs[r*DIM + d];
                a0[r] += xv * w0; a1[r] += xv * w1v; a2[r] += xv * w2v;
            }
        }
#pragma unroll
        for (int r = 0; r < 16; r++) {
            qkvs[r*QS + tid]       = a0[r];
            qkvs[r*QS + tid + 256] = a1[r];
            qkvs[r*QS + tid + 512] = a2[r];
        }
    }
    __syncthreads();
    /* --- attention: warp h handles head h --- */
    int h = tid >> 5, lane = tid & 31;
    float* kk = wbuf + h*1024;         /* kk[m][d] = k[m][d] + pos_q[m][d] */
    float* pk = kk + 512;              /* pk[m][d] = pos_k[m][d] */
    int hoff = h * HD;
    const float* pq_g = &g_pos[0][(long)b*NS][0];
    const float* pk_g = &g_pos[1][(long)b*NS][0];
    const float* pv_g = &g_pos[2][(long)b*NS][0];
    for (int i = lane; i < 512; i += 32) {
        int m = i >> 5, d = i & 31;
        kk[i] = qkvs[m*QS + 256 + hoff + d] + pq_g[m*DIM + hoff + d];
        pk[i] = pk_g[m*DIM + hoff + d];
    }
    __syncwarp();
    int n = lane & 15, mg = lane >> 4;  /* lane -> (row n, m-half mg) */
    float dd[8];
#pragma unroll
    for (int i = 0; i < 8; i++) dd[i] = 0.f;
    for (int d = 0; d < HD; d++) {
        float qv = qkvs[n*QS + hoff + d];
        float kv = qkvs[n*QS + 256 + hoff + d];
#pragma unroll
        for (int mm = 0; mm < 8; mm++) {
            int m = mg*8 + mm;
            dd[mm] += qv * kk[m*32 + d] + kv * pk[m*32 + d];
        }
    }
    float mx = dd[0];
#pragma unroll
    for (int mm = 1; mm < 8; mm++) mx = fmaxf(mx, dd[mm]);
    mx = fmaxf(mx, __shfl_xor_sync(0xffffffffu, mx, 16));
    float e[8], ssum = 0.f;
#pragma unroll
    for (int mm = 0; mm < 8; mm++) { e[mm] = __expf((dd[mm] - mx) * ATT_SCALE); ssum += e[mm]; }
    ssum += __shfl_xor_sync(0xffffffffu, ssum, 16);
    float inv = 1.f / ssum;
    float* at = ats + h*272;           /* 16 x 17 padded */
#pragma unroll
    for (int mm = 0; mm < 8; mm++) at[n*17 + mg*8 + mm] = e[mm] * inv;
    __syncwarp();
    /* vv = v + pos_v (reuse kk) */
    for (int i = lane; i < 512; i += 32) {
        int m = i >> 5, d = i & 31;
        kk[i] = qkvs[m*QS + 512 + hoff + d] + pv_g[m*DIM + hoff + d];
    }
    __syncwarp();
    int dg = mg;                        /* lane -> (row n, d-half dg) */
    float o[16];
#pragma unroll
    for (int i = 0; i < 16; i++) o[i] = 0.f;
    for (int m = 0; m < 16; m++) {
        float a = at[n*17 + m];
#pragma unroll
        for (int i = 0; i < 16; i++) o[i] += a * kk[m*32 + dg*16 + i];
    }
#pragma unroll
    for (int i = 0; i < 16; i++) xs[n*DIM + hoff + dg*16 + i] = o[i];
    __syncthreads();
    /* --- proj: out = attn_out @ proj_w.T + proj_b --- */
    {
        float acc[16];
#pragma unroll
        for (int r = 0; r < 16; r++) acc[r] = 0.f;
        const float* pt = &g_projT[0][0];
        for (int d = 0; d < DIM; d++) {
            float w = pt[d*DIM + tid];
#pragma unroll
            for (int r = 0; r < 16; r++) acc[r] += xs[r*DIM + d] * w;
        }
        float bbv = projb[tid];
        float* ob = out + (long)b * NS * DIM;
#pragma unroll
        for (int r = 0; r < 16; r++) ob[r*DIM + tid] = acc[r] + bbv;
    }
}

/* ---------------- launcher ---------------- */
extern "C" void kernel_launch(void* const* d_in, const int* in_sizes, int n_in,
                              void* d_out, int out_size) {
    (void)in_sizes; (void)n_in; (void)out_size;
    const float* x     = (const float*)d_in[0];
    const float* pr    = (const float*)d_in[1];
    const float* qkvw  = (const float*)d_in[2];
    const float* projw = (const float*)d_in[3];
    const float* projb = (const float*)d_in[4];
    const float* qw1 = (const float*)d_in[5];
    const float* qb1 = (const float*)d_in[6];
    const float* qg  = (const float*)d_in[7];
    const float* qbe = (const float*)d_in[8];
    const float* qw2 = (const float*)d_in[9];
    const float* qb2 = (const float*)d_in[10];
    const float* kw1 = (const float*)d_in[11];
    const float* kb1 = (const float*)d_in[12];
    const float* kg  = (const float*)d_in[13];
    const float* kbe = (const float*)d_in[14];
    const float* kw2 = (const float*)d_in[15];
    const float* kb2 = (const float*)d_in[16];
    const float* vw1 = (const float*)d_in[17];
    const float* vb1 = (const float*)d_in[18];
    const float* vg  = (const float*)d_in[19];
    const float* vbe = (const float*)d_in[20];
    const float* vw2 = (const float*)d_in[21];
    const float* vb2 = (const float*)d_in[22];

    const int smem_posmlp = (64*PF + 64*DIM) * 4;                 /* 77824 B */
    const int smem_main   = (4096 + 16*QS + 8*1024 + 8*272) * 4;  /* 107136 B */
    cudaFuncSetAttribute(k_posmlp, cudaFuncAttributeMaxDynamicSharedMemorySize, smem_posmlp);
    cudaFuncSetAttribute(k_main,   cudaFuncAttributeMaxDynamicSharedMemorySize, smem_main);

    k_stats_part<<<256, 256>>>(pr);
    k_stats_red<<<10, 256>>>();
    k_prep<<<896, 512>>>(qkvw, qw2, kw2, vw2, projw);
    k_fold<<<96, 256>>>(qw1, qb1, qg, qbe, kw1, kb1, kg, kbe, vw1, vb1, vg, vbe);
    k_posmlp<<<NROWS/64, 256, smem_posmlp>>>(pr, qb2, kb2, vb2);
    k_main<<<NBATCH, 256, smem_main>>>(x, projb, (float*)d_out);
}

// round 3
// speedup vs baseline: 2.5932x; 2.5932x over previous
#include <cuda_runtime.h>
#include <stdint.h>
#include <math.h>

#define NBATCH 8192
#define NS 16
#define DIM 256
#define PF 48
#define NROWS (NBATCH*NS)   /* 131072 */
#define EPSC 1e-5f
#define ATT_SCALE 0.17677669529663687f
#define HSTR 260            /* smem stride for 256-wide fp32 tiles (conflict-free A loads) */
#define PSTR 52             /* smem stride for 48-wide pr tile */
#define BSTR 136            /* smem stride for 128-wide B tiles (conflict-free B-frag loads) */

/* ---------------- device scratch ---------------- */
__device__ float g_part_S[256][PF*PF];
__device__ float g_part_m[256][PF];
__device__ float g_S[PF*PF];
__device__ float g_m[PF];
__device__ float g_w1T[3][PF][DIM];       /* BN-folded layer-1 weight, transposed, tf32 */
__device__ float g_b1e[3][DIM];
__device__ float g_qkvT[DIM][3*DIM];      /* tf32 */
__device__ float g_w2T[3][DIM][DIM];      /* tf32 */
__device__ float g_projT[DIM][DIM];       /* tf32 */
__device__ float g_pos[3][NROWS][DIM];
__device__ float g_qkv[NROWS][3*DIM];

__device__ __forceinline__ float to_tf32(float x) {
    uint32_t u; asm("cvt.rna.tf32.f32 %0, %1;" : "=r"(u) : "f"(x));
    return __uint_as_float(u);
}
__device__ __forceinline__ void mma_tf32(float& c0, float& c1, float& c2, float& c3,
                                         uint32_t a0, uint32_t a1, uint32_t a2, uint32_t a3,
                                         uint32_t b0, uint32_t b1) {
    asm volatile("mma.sync.aligned.m16n8k8.row.col.f32.tf32.tf32.f32 "
                 "{%0,%1,%2,%3},{%4,%5,%6,%7},{%8,%9},{%0,%1,%2,%3};"
                 : "+f"(c0), "+f"(c1), "+f"(c2), "+f"(c3)
                 : "r"(a0), "r"(a1), "r"(a2), "r"(a3), "r"(b0), "r"(b1));
}

/* ---------------- 1) partial stats ---------------- */
__global__ void k_stats_part(const float* __restrict__ pr) {
    __shared__ float ps[64*PF];
    int tid = threadIdx.x;
    int ti = tid >> 4, tj = tid & 15;
    float acc[9]; float asum[3];
#pragma unroll
    for (int i = 0; i < 9; i++) acc[i] = 0.f;
    asum[0] = asum[1] = asum[2] = 0.f;
    int r0 = blockIdx.x * 512;
    for (int t = 0; t < 8; t++) {
        const float* src = pr + (long)(r0 + t*64) * PF;
        for (int i = tid; i < 64*PF; i += 256) ps[i] = src[i];
        __syncthreads();
        for (int r = 0; r < 64; r++) {
            float si0 = ps[r*PF + 3*ti + 0];
            float si1 = ps[r*PF + 3*ti + 1];
            float si2 = ps[r*PF + 3*ti + 2];
            float sj0 = ps[r*PF + 3*tj + 0];
            float sj1 = ps[r*PF + 3*tj + 1];
            float sj2 = ps[r*PF + 3*tj + 2];
            acc[0] += si0*sj0; acc[1] += si0*sj1; acc[2] += si0*sj2;
            acc[3] += si1*sj0; acc[4] += si1*sj1; acc[5] += si1*sj2;
            acc[6] += si2*sj0; acc[7] += si2*sj1; acc[8] += si2*sj2;
            if (tj == 0) { asum[0] += si0; asum[1] += si1; asum[2] += si2; }
        }
        __syncthreads();
    }
#pragma unroll
    for (int a = 0; a < 3; a++)
#pragma unroll
        for (int bq = 0; bq < 3; bq++)
            g_part_S[blockIdx.x][(3*ti + a)*PF + 3*tj + bq] = acc[a*3 + bq];
    if (tj == 0) {
        g_part_m[blockIdx.x][3*ti + 0] = asum[0];
        g_part_m[blockIdx.x][3*ti + 1] = asum[1];
        g_part_m[blockIdx.x][3*ti + 2] = asum[2];
    }
}

/* ---------------- 2) final reduce ---------------- */
__global__ void k_stats_red() {
    int i = blockIdx.x * 256 + threadIdx.x;
    if (i < PF*PF) {
        float s = 0.f;
        for (int c = 0; c < 256; c++) s += g_part_S[c][i];
        g_S[i] = s;
    } else if (i < PF*PF + PF) {
        int j = i - PF*PF;
        float s = 0.f;
        for (int c = 0; c < 256; c++) s += g_part_m[c][j];
        g_m[j] = s * (1.f / (float)NROWS);
    }
}

/* ---------------- 3) transpose + tf32-round weights ---------------- */
__global__ void k_prep(const float* __restrict__ qkvw, const float* __restrict__ w2q,
                       const float* __restrict__ w2k, const float* __restrict__ w2v,
                       const float* __restrict__ projw) {
    int idx = blockIdx.x * blockDim.x + threadIdx.x;
    const int T0 = 768*256;
    const int T1 = T0 + 3*256*256;
    const int TT = T1 + 256*256;
    for (; idx < TT; idx += gridDim.x * blockDim.x) {
        if (idx < T0) {
            int d = idx / 768, c = idx % 768;
            g_qkvT[d][c] = to_tf32(qkvw[c*256 + d]);
        } else if (idx < T1) {
            int l = idx - T0;
            int p = l >> 16; l &= 65535;
            int d = l >> 8, c = l & 255;
            const float* w = (p == 0 ? w2q : (p == 1 ? w2k : w2v));
            g_w2T[p][d][c] = to_tf32(w[c*256 + d]);
        } else {
            int l = idx - T1;
            int d = l >> 8, c = l & 255;
            g_projT[d][c] = to_tf32(projw[c*256 + d]);
        }
    }
}

/* ---------------- 4) fold BN into layer-1 affine ---------------- */
__global__ void k_fold(const float* __restrict__ qw1, const float* __restrict__ qb1,
                       const float* __restrict__ qg,  const float* __restrict__ qbe,
                       const float* __restrict__ kw1, const float* __restrict__ kb1,
                       const float* __restrict__ kg,  const float* __restrict__ kbe,
                       const float* __restrict__ vw1, const float* __restrict__ vb1,
                       const float* __restrict__ vg,  const float* __restrict__ vbe) {
    __shared__ float ws[8][PF];
    int tid = threadIdx.x;
    int wl = tid >> 5, lane = tid & 31;
    int ch = blockIdx.x * 8 + wl;
    int p = ch >> 8, c = ch & 255;
    const float* w1 = (p == 0 ? qw1 : (p == 1 ? kw1 : vw1)) + c*PF;
    const float* b1 = (p == 0 ? qb1 : (p == 1 ? kb1 : vb1));
    const float* gg = (p == 0 ? qg  : (p == 1 ? kg  : vg ));
    const float* be = (p == 0 ? qbe : (p == 1 ? kbe : vbe));
    ws[wl][lane] = w1[lane];
    if (lane < PF - 32) ws[wl][lane + 32] = w1[lane + 32];
    __syncwarp();
    float quad = 0.f, wm = 0.f;
#pragma unroll
    for (int ii = 0; ii < 2; ii++) {
        int i = lane + ii*32;
        if (i < PF) {
            float wi = ws[wl][i];
            float t = 0.f;
            for (int j = 0; j < PF; j++) t += g_S[i*PF + j] * ws[wl][j];
            quad += wi * t;
            wm   += wi * g_m[i];
        }
    }
    for (int off = 16; off > 0; off >>= 1) {
        quad += __shfl_xor_sync(0xffffffffu, quad, off);
        wm   += __shfl_xor_sync(0xffffffffu, wm,   off);
    }
    float var   = quad * (1.f / (float)NROWS) - wm * wm;
    float scale = gg[c] * rsqrtf(var + EPSC);
    float mu    = wm + b1[c];
    float b1e   = (b1[c] - mu) * scale + be[c];
#pragma unroll
    for (int ii = 0; ii < 2; ii++) {
        int j = lane + ii*32;
        if (j < PF) g_w1T[p][j][c] = to_tf32(ws[wl][j] * scale);
    }
    if (lane == 0) g_b1e[p][c] = b1e;
}

/* ---------------- 5) pos MLPs via tf32 mma: relu(pos@W1eff+b1e)@w2+b2 ---------------- */
__global__ void __launch_bounds__(512, 1) k_posmlp(const float* __restrict__ pr,
        const float* __restrict__ qb2, const float* __restrict__ kb2,
        const float* __restrict__ vb2) {
    extern __shared__ float sm[];
    float* prs = sm;                       /* 128 x PSTR */
    float* hs  = sm + 128*PSTR;            /* 128 x HSTR */
    float* bs  = hs + 128*HSTR;            /* 2 x 32 x BSTR */
    int tid = threadIdx.x;
    int wid = tid >> 5, lane = tid & 31;
    int mg = wid >> 1, nh = wid & 1;       /* warp -> (row group, n half) */
    int g = lane >> 2, t = lane & 3;
    int r0 = blockIdx.x * 128;
    int arow = mg*16 + g;

    /* load pr tile, tf32-rounded */
    for (int i4 = tid; i4 < 128*12; i4 += 512) {
        int row = i4 / 12, c4 = i4 % 12;
        float4 v = *(const float4*)(pr + (long)(r0 + row)*PF + c4*4);
        float* d = prs + row*PSTR + c4*4;
        d[0] = to_tf32(v.x); d[1] = to_tf32(v.y); d[2] = to_tf32(v.z); d[3] = to_tf32(v.w);
    }
    __syncthreads();

    for (int p = 0; p < 3; p++) {
        const float* w1 = &g_w1T[p][0][0];
        const float* b1 = g_b1e[p];
        /* ---- layer 1: [128x48]@[48x256] -> relu -> hs ---- */
        for (int nc = 0; nc < 2; nc++) {
            __syncthreads();
            for (int i4 = tid; i4 < 48*32; i4 += 512) {
                int row = i4 >> 5, c4 = i4 & 31;
                *(float4*)(bs + row*BSTR + c4*4) =
                    *(const float4*)(w1 + row*DIM + nc*128 + c4*4);
            }
            __syncthreads();
            float acc[8][4];
#pragma unroll
            for (int nb = 0; nb < 8; nb++) { acc[nb][0]=acc[nb][1]=acc[nb][2]=acc[nb][3]=0.f; }
#pragma unroll
            for (int k = 0; k < PF; k += 8) {
                uint32_t a0 = __float_as_uint(prs[arow*PSTR + k + t]);
                uint32_t a1 = __float_as_uint(prs[(arow+8)*PSTR + k + t]);
                uint32_t a2 = __float_as_uint(prs[arow*PSTR + k + 4 + t]);
                uint32_t a3 = __float_as_uint(prs[(arow+8)*PSTR + k + 4 + t]);
#pragma unroll
                for (int nb = 0; nb < 8; nb++) {
                    int cb = nh*64 + nb*8 + g;
                    uint32_t b0 = __float_as_uint(bs[(k + t)*BSTR + cb]);
                    uint32_t b1v = __float_as_uint(bs[(k + 4 + t)*BSTR + cb]);
                    mma_tf32(acc[nb][0], acc[nb][1], acc[nb][2], acc[nb][3],
                             a0, a1, a2, a3, b0, b1v);
                }
            }
#pragma unroll
            for (int nb = 0; nb < 8; nb++) {
                int col = nc*128 + nh*64 + nb*8 + 2*t;
                float bb0 = __ldg(&b1[col]), bb1 = __ldg(&b1[col+1]);
                hs[arow*HSTR + col]       = to_tf32(fmaxf(acc[nb][0] + bb0, 0.f));
                hs[arow*HSTR + col + 1]   = to_tf32(fmaxf(acc[nb][1] + bb1, 0.f));
                hs[(arow+8)*HSTR + col]   = to_tf32(fmaxf(acc[nb][2] + bb0, 0.f));
                hs[(arow+8)*HSTR + col+1] = to_tf32(fmaxf(acc[nb][3] + bb1, 0.f));
            }
        }
        /* ---- layer 2: [128x256]@[256x256] + b2 -> g_pos[p] ---- */
        const float* w2 = &g_w2T[p][0][0];
        const float* b2 = (p == 0 ? qb2 : (p == 1 ? kb2 : vb2));
        for (int nc = 0; nc < 2; nc++) {
            __syncthreads();
            for (int i4 = tid; i4 < 32*32; i4 += 512) {
                int row = i4 >> 5, c4 = i4 & 31;
                *(float4*)(bs + row*BSTR + c4*4) =
                    *(const float4*)(w2 + row*DIM + nc*128 + c4*4);
            }
            __syncthreads();
            float acc[8][4];
#pragma unroll
            for (int nb = 0; nb < 8; nb++) { acc[nb][0]=acc[nb][1]=acc[nb][2]=acc[nb][3]=0.f; }
            for (int ks = 0; ks < 8; ks++) {
                float* bcur = bs + (ks & 1)*32*BSTR;
                if (ks < 7) {
                    float* bnxt = bs + ((ks + 1) & 1)*32*BSTR;
                    for (int i4 = tid; i4 < 32*32; i4 += 512) {
                        int row = i4 >> 5, c4 = i4 & 31;
                        *(float4*)(bnxt + row*BSTR + c4*4) =
                            *(const float4*)(w2 + ((ks+1)*32 + row)*DIM + nc*128 + c4*4);
                    }
                }
#pragma unroll
                for (int kk = 0; kk < 4; kk++) {
                    int k = ks*32 + kk*8;
                    uint32_t a0 = __float_as_uint(hs[arow*HSTR + k + t]);
                    uint32_t a1 = __float_as_uint(hs[(arow+8)*HSTR + k + t]);
                    uint32_t a2 = __float_as_uint(hs[arow*HSTR + k + 4 + t]);
                    uint32_t a3 = __float_as_uint(hs[(arow+8)*HSTR + k + 4 + t]);
#pragma unroll
                    for (int nb = 0; nb < 8; nb++) {
                        int cb = nh*64 + nb*8 + g;
                        uint32_t b0 = __float_as_uint(bcur[(kk*8 + t)*BSTR + cb]);
                        uint32_t b1v = __float_as_uint(bcur[(kk*8 + 4 + t)*BSTR + cb]);
                        mma_tf32(acc[nb][0], acc[nb][1], acc[nb][2], acc[nb][3],
                                 a0, a1, a2, a3, b0, b1v);
                    }
                }
                __syncthreads();
            }
#pragma unroll
            for (int nb = 0; nb < 8; nb++) {
                int col = nc*128 + nh*64 + nb*8 + 2*t;
                float bb0 = __ldg(&b2[col]), bb1 = __ldg(&b2[col+1]);
                long gr = r0 + arow;
                *(float2*)(&g_pos[p][gr][col])     = make_float2(acc[nb][0]+bb0, acc[nb][1]+bb1);
                *(float2*)(&g_pos[p][gr + 8][col]) = make_float2(acc[nb][2]+bb0, acc[nb][3]+bb1);
            }
        }
    }
}

/* ---------------- 6) qkv GEMM via tf32 mma -> g_qkv ---------------- */
__global__ void __launch_bounds__(512, 1) k_qkv(const float* __restrict__ x) {
    extern __shared__ float sm[];
    float* xs = sm;                        /* 128 x HSTR */
    float* bs = sm + 128*HSTR;             /* 2 x 32 x BSTR */
    int tid = threadIdx.x;
    int wid = tid >> 5, lane = tid & 31;
    int mg = wid >> 1, nh = wid & 1;
    int g = lane >> 2, t = lane & 3;
    int r0 = blockIdx.x * 128;
    int arow = mg*16 + g;

    for (int i4 = tid; i4 < 128*64; i4 += 512) {
        int row = i4 >> 6, c4 = i4 & 63;
        float4 v = *(const float4*)(x + (long)(r0 + row)*DIM + c4*4);
        float* d = xs + row*HSTR + c4*4;
        d[0] = to_tf32(v.x); d[1] = to_tf32(v.y); d[2] = to_tf32(v.z); d[3] = to_tf32(v.w);
    }
    __syncthreads();

    for (int nc = 0; nc < 6; nc++) {
        __syncthreads();
        for (int i4 = tid; i4 < 32*32; i4 += 512) {
            int row = i4 >> 5, c4 = i4 & 31;
            *(float4*)(bs + row*BSTR + c4*4) =
                *(const float4*)(&g_qkvT[row][nc*128 + c4*4]);
        }
        __syncthreads();
        float acc[8][4];
#pragma unroll
        for (int nb = 0; nb < 8; nb++) { acc[nb][0]=acc[nb][1]=acc[nb][2]=acc[nb][3]=0.f; }
        for (int ks = 0; ks < 8; ks++) {
            float* bcur = bs + (ks & 1)*32*BSTR;
            if (ks < 7) {
                float* bnxt = bs + ((ks + 1) & 1)*32*BSTR;
                for (int i4 = tid; i4 < 32*32; i4 += 512) {
                    int row = i4 >> 5, c4 = i4 & 31;
                    *(float4*)(bnxt + row*BSTR + c4*4) =
                        *(const float4*)(&g_qkvT[(ks+1)*32 + row][nc*128 + c4*4]);
                }
            }
#pragma unroll
            for (int kk = 0; kk < 4; kk++) {
                int k = ks*32 + kk*8;
                uint32_t a0 = __float_as_uint(xs[arow*HSTR + k + t]);
                uint32_t a1 = __float_as_uint(xs[(arow+8)*HSTR + k + t]);
                uint32_t a2 = __float_as_uint(xs[arow*HSTR + k + 4 + t]);
                uint32_t a3 = __float_as_uint(xs[(arow+8)*HSTR + k + 4 + t]);
#pragma unroll
                for (int nb = 0; nb < 8; nb++) {
                    int cb = nh*64 + nb*8 + g;
                    uint32_t b0 = __float_as_uint(bcur[(kk*8 + t)*BSTR + cb]);
                    uint32_t b1v = __float_as_uint(bcur[(kk*8 + 4 + t)*BSTR + cb]);
                    mma_tf32(acc[nb][0], acc[nb][1], acc[nb][2], acc[nb][3],
                             a0, a1, a2, a3, b0, b1v);
                }
            }
            __syncthreads();
        }
#pragma unroll
        for (int nb = 0; nb < 8; nb++) {
            int col = nc*128 + nh*64 + nb*8 + 2*t;
            long gr = r0 + arow;
            *(float2*)(&g_qkv[gr][col])     = make_float2(acc[nb][0], acc[nb][1]);
            *(float2*)(&g_qkv[gr + 8][col]) = make_float2(acc[nb][2], acc[nb][3]);
        }
    }
}

/* ---------------- 7) attention (fp32) + proj GEMM (tf32 mma), fused ---------------- */
__global__ void __launch_bounds__(256, 1) k_attnproj(const float* __restrict__ projb,
                                                     float* __restrict__ out) {
    extern __shared__ float sm[];
    float* xs = sm;                        /* 128 x HSTR : attn out (tf32) */
    float* bs = sm + 128*HSTR;             /* 2 x 16 x BSTR */
    float* wb = bs + 2*16*BSTR;            /* 8 warps x 2080 */
    int tid = threadIdx.x;
    int w = tid >> 5, lane = tid & 31;
    float* kk = wb + w*2080;               /* [16][32] k+pos_q, later v+pos_v */
    float* pk = kk + 512;                  /* [16][32] pos_k */
    float* qb = pk + 512;                  /* [16][33] q ; reused as at[16][17] */
    float* kn = qb + 528;                  /* [16][33] raw k (n-indexed) */
    float* at = qb;
    long row0 = (long)blockIdx.x*128 + w*16;
    int n = lane & 15, mgh = lane >> 4;

    for (int h = 0; h < 8; h++) {
        int ho = h*32;
        for (int i = lane; i < 512; i += 32) {
            int m = i >> 5, d = i & 31;
            float kraw = g_qkv[row0 + m][256 + ho + d];
            kk[i] = kraw + g_pos[0][row0 + m][ho + d];
            pk[i] = g_pos[1][row0 + m][ho + d];
            kn[m*33 + d] = kraw;
            qb[m*33 + d] = g_qkv[row0 + m][ho + d];
        }
        __syncwarp();
        float dd[8];
#pragma unroll
        for (int i = 0; i < 8; i++) dd[i] = 0.f;
        for (int d = 0; d < 32; d++) {
            float qv = qb[n*33 + d];
            float kv = kn[n*33 + d];
#pragma unroll
            for (int mm = 0; mm < 8; mm++) {
                int m = mgh*8 + mm;
                dd[mm] += qv * kk[m*32 + d] + kv * pk[m*32 + d];
            }
        }
        float mx = dd[0];
#pragma unroll
        for (int mm = 1; mm < 8; mm++) mx = fmaxf(mx, dd[mm]);
        mx = fmaxf(mx, __shfl_xor_sync(0xffffffffu, mx, 16));
        float e[8], ssum = 0.f;
#pragma unroll
        for (int mm = 0; mm < 8; mm++) { e[mm] = __expf((dd[mm] - mx) * ATT_SCALE); ssum += e[mm]; }
        ssum += __shfl_xor_sync(0xffffffffu, ssum, 16);
        float inv = 1.f / ssum;
        __syncwarp();
#pragma unroll
        for (int mm = 0; mm < 8; mm++) at[n*17 + mgh*8 + mm] = e[mm] * inv;
        __syncwarp();
        for (int i = lane; i < 512; i += 32) {
            int m = i >> 5, d = i & 31;
            kk[i] = g_qkv[row0 + m][512 + ho + d] + g_pos[2][row0 + m][ho + d];
        }
        __syncwarp();
        float o[16];
#pragma unroll
        for (int i = 0; i < 16; i++) o[i] = 0.f;
        for (int m = 0; m < 16; m++) {
            float a = at[n*17 + m];
#pragma unroll
            for (int i = 0; i < 16; i++) o[i] += a * kk[m*32 + mgh*16 + i];
        }
#pragma unroll
        for (int i = 0; i < 16; i++)
            xs[(w*16 + n)*HSTR + ho + mgh*16 + i] = to_tf32(o[i]);
        __syncwarp();
    }
    __syncthreads();

    /* proj: [128x256]@[256x256] + proj_b */
    int g = lane >> 2, t = lane & 3;
    int arow = w*16 + g;
    const float* pw = &g_projT[0][0];
    for (int nc = 0; nc < 2; nc++) {
        __syncthreads();
        for (int i4 = tid; i4 < 16*32; i4 += 256) {
            int row = i4 >> 5, c4 = i4 & 31;
            *(float4*)(bs + row*BSTR + c4*4) =
                *(const float4*)(pw + row*DIM + nc*128 + c4*4);
        }
        __syncthreads();
        float acc[16][4];
#pragma unroll
        for (int nb = 0; nb < 16; nb++) { acc[nb][0]=acc[nb][1]=acc[nb][2]=acc[nb][3]=0.f; }
        for (int ks = 0; ks < 16; ks++) {
            float* bcur = bs + (ks & 1)*16*BSTR;
            if (ks < 15) {
                float* bnxt = bs + ((ks + 1) & 1)*16*BSTR;
                for (int i4 = tid; i4 < 16*32; i4 += 256) {
                    int row = i4 >> 5, c4 = i4 & 31;
                    *(float4*)(bnxt + row*BSTR + c4*4) =
                        *(const float4*)(pw + ((ks+1)*16 + row)*DIM + nc*128 + c4*4);
                }
            }
#pragma unroll
            for (int kk2 = 0; kk2 < 2; kk2++) {
                int k = ks*16 + kk2*8;
                uint32_t a0 = __float_as_uint(xs[arow*HSTR + k + t]);
                uint32_t a1 = __float_as_uint(xs[(arow+8)*HSTR + k + t]);
                uint32_t a2 = __float_as_uint(xs[arow*HSTR + k + 4 + t]);
                uint32_t a3 = __float_as_uint(xs[(arow+8)*HSTR + k + 4 + t]);
#pragma unroll
                for (int nb = 0; nb < 16; nb++) {
                    int cb = nb*8 + g;
                    uint32_t b0 = __float_as_uint(bcur[(kk2*8 + t)*BSTR + cb]);
                    uint32_t b1v = __float_as_uint(bcur[(kk2*8 + 4 + t)*BSTR + cb]);
                    mma_tf32(acc[nb][0], acc[nb][1], acc[nb][2], acc[nb][3],
                             a0, a1, a2, a3, b0, b1v);
                }
            }
            __syncthreads();
        }
#pragma unroll
        for (int nb = 0; nb < 16; nb++) {
            int col = nc*128 + nb*8 + 2*t;
            float bb0 = __ldg(&projb[col]), bb1 = __ldg(&projb[col+1]);
            long gr = (long)blockIdx.x*128 + arow;
            *(float2*)(&out[gr*DIM + col])       = make_float2(acc[nb][0]+bb0, acc[nb][1]+bb1);
            *(float2*)(&out[(gr + 8)*DIM + col]) = make_float2(acc[nb][2]+bb0, acc[nb][3]+bb1);
        }
    }
}

/* ---------------- launcher ---------------- */
extern "C" void kernel_launch(void* const* d_in, const int* in_sizes, int n_in,
                              void* d_out, int out_size) {
    (void)in_sizes; (void)n_in; (void)out_size;
    const float* x     = (const float*)d_in[0];
    const float* pr    = (const float*)d_in[1];
    const float* qkvw  = (const float*)d_in[2];
    const float* projw = (const float*)d_in[3];
    const float* projb = (const float*)d_in[4];
    const float* qw1 = (const float*)d_in[5];
    const float* qb1 = (const float*)d_in[6];
    const float* qg  = (const float*)d_in[7];
    const float* qbe = (const float*)d_in[8];
    const float* qw2 = (const float*)d_in[9];
    const float* qb2 = (const float*)d_in[10];
    const float* kw1 = (const float*)d_in[11];
    const float* kb1 = (const float*)d_in[12];
    const float* kg  = (const float*)d_in[13];
    const float* kbe = (const float*)d_in[14];
    const float* kw2 = (const float*)d_in[15];
    const float* kb2 = (const float*)d_in[16];
    const float* vw1 = (const float*)d_in[17];
    const float* vb1 = (const float*)d_in[18];
    const float* vg  = (const float*)d_in[19];
    const float* vbe = (const float*)d_in[20];
    const float* vw2 = (const float*)d_in[21];
    const float* vb2 = (const float*)d_in[22];

    const int smem_posmlp = (128*PSTR + 128*HSTR + 2*32*BSTR) * 4;   /* 194560 */
    const int smem_qkv    = (128*HSTR + 2*32*BSTR) * 4;              /* 167936 */
    const int smem_ap     = (128*HSTR + 2*16*BSTR + 8*2080) * 4;     /* 217088 */
    cudaFuncSetAttribute(k_posmlp,  cudaFuncAttributeMaxDynamicSharedMemorySize, smem_posmlp);
    cudaFuncSetAttribute(k_qkv,     cudaFuncAttributeMaxDynamicSharedMemorySize, smem_qkv);
    cudaFuncSetAttribute(k_attnproj,cudaFuncAttributeMaxDynamicSharedMemorySize, smem_ap);

    k_stats_part<<<256, 256>>>(pr);
    k_stats_red<<<10, 256>>>();
    k_prep<<<896, 512>>>(qkvw, qw2, kw2, vw2, projw);
    k_fold<<<96, 256>>>(qw1, qb1, qg, qbe, kw1, kb1, kg, kbe, vw1, vb1, vg, vbe);
    k_posmlp<<<NROWS/128, 512, smem_posmlp>>>(pr, qb2, kb2, vb2);
    k_qkv<<<NROWS/128, 512, smem_qkv>>>(x);
    k_attnproj<<<NROWS/128, 256, smem_ap>>>(projb, (float*)d_out);
}

// round 4
// speedup vs baseline: 4.4934x; 1.7328x over previous
#include <cuda_runtime.h>
#include <cuda_fp16.h>
#include <stdint.h>
#include <math.h>

#define NBATCH 8192
#define NS 16
#define DIM 256
#define PF 48
#define NROWS (NBATCH*NS)   /* 131072 */
#define EPSC 1e-5f
#define ATT_SCALE 0.17677669529663687f
#define PSH 56    /* prs stride (halves): 48 cols padded; word stride 28 -> banks 4g..+t distinct */
#define HSH 264   /* 256-col fp16 A tiles stride (halves): word stride 132 -> 4g+t distinct */
#define B1SH 56   /* layer1 B stride (halves) */
#define B2SH 72   /* 64-col k-chunk B stride (halves): word stride 36 -> 4g+t distinct */

/* ---------------- device scratch ---------------- */
__device__ float g_part_S[256][PF*PF];
__device__ float g_part_m[256][PF];
__device__ float g_S[PF*PF];
__device__ float g_m[PF];
__device__ __half g_w1h[3][256*PF];        /* BN-folded layer-1 weight, [n][k] fp16 */
__device__ float  g_b1e[3][DIM];
__device__ __half g_qkvwh[768*256];        /* qkv_w [n][k] fp16 */
__device__ __half g_w2h[3][256*256];       /* w2 [n][k] fp16 */
__device__ __half g_projh[256*256];        /* proj_w [n][k] fp16 */
__device__ __half g_posh[3][(long)NROWS*256];
__device__ __half g_qkvh[(long)NROWS*768];

__device__ __forceinline__ void mma_f16(float& c0, float& c1, float& c2, float& c3,
                                        uint32_t a0, uint32_t a1, uint32_t a2, uint32_t a3,
                                        uint32_t b0, uint32_t b1) {
    asm volatile("mma.sync.aligned.m16n8k16.row.col.f32.f16.f16.f32 "
                 "{%0,%1,%2,%3},{%4,%5,%6,%7},{%8,%9},{%0,%1,%2,%3};"
                 : "+f"(c0), "+f"(c1), "+f"(c2), "+f"(c3)
                 : "r"(a0), "r"(a1), "r"(a2), "r"(a3), "r"(b0), "r"(b1));
}
__device__ __forceinline__ uint32_t ldh2(const __half* p) {
    return *(const uint32_t*)p;
}

/* ---------------- 1) partial stats ---------------- */
__global__ void k_stats_part(const float* __restrict__ pr) {
    __shared__ float ps[64*PF];
    int tid = threadIdx.x;
    int ti = tid >> 4, tj = tid & 15;
    float acc[9]; float asum[3];
#pragma unroll
    for (int i = 0; i < 9; i++) acc[i] = 0.f;
    asum[0] = asum[1] = asum[2] = 0.f;
    int r0 = blockIdx.x * 512;
    for (int t = 0; t < 8; t++) {
        const float* src = pr + (long)(r0 + t*64) * PF;
        for (int i = tid; i < 64*PF; i += 256) ps[i] = src[i];
        __syncthreads();
        for (int r = 0; r < 64; r++) {
            float si0 = ps[r*PF + 3*ti + 0];
            float si1 = ps[r*PF + 3*ti + 1];
            float si2 = ps[r*PF + 3*ti + 2];
            float sj0 = ps[r*PF + 3*tj + 0];
            float sj1 = ps[r*PF + 3*tj + 1];
            float sj2 = ps[r*PF + 3*tj + 2];
            acc[0] += si0*sj0; acc[1] += si0*sj1; acc[2] += si0*sj2;
            acc[3] += si1*sj0; acc[4] += si1*sj1; acc[5] += si1*sj2;
            acc[6] += si2*sj0; acc[7] += si2*sj1; acc[8] += si2*sj2;
            if (tj == 0) { asum[0] += si0; asum[1] += si1; asum[2] += si2; }
        }
        __syncthreads();
    }
#pragma unroll
    for (int a = 0; a < 3; a++)
#pragma unroll
        for (int bq = 0; bq < 3; bq++)
            g_part_S[blockIdx.x][(3*ti + a)*PF + 3*tj + bq] = acc[a*3 + bq];
    if (tj == 0) {
        g_part_m[blockIdx.x][3*ti + 0] = asum[0];
        g_part_m[blockIdx.x][3*ti + 1] = asum[1];
        g_part_m[blockIdx.x][3*ti + 2] = asum[2];
    }
}

/* ---------------- 2) final reduce ---------------- */
__global__ void k_stats_red() {
    int i = blockIdx.x * 256 + threadIdx.x;
    if (i < PF*PF) {
        float s = 0.f;
        for (int c = 0; c < 256; c++) s += g_part_S[c][i];
        g_S[i] = s;
    } else if (i < PF*PF + PF) {
        int j = i - PF*PF;
        float s = 0.f;
        for (int c = 0; c < 256; c++) s += g_part_m[c][j];
        g_m[j] = s * (1.f / (float)NROWS);
    }
}

/* ---------------- 3) fp32 -> fp16 weight convert (no transposes needed) ---------------- */
__global__ void k_prep(const float* __restrict__ qkvw, const float* __restrict__ w2q,
                       const float* __restrict__ w2k, const float* __restrict__ w2v,
                       const float* __restrict__ projw) {
    int i4 = blockIdx.x * blockDim.x + threadIdx.x;   /* float4 index */
    const int N0 = 768*256/4;          /* 49152 */
    const int N1 = N0 + 3*65536/4;     /* + 49152 */
    const int NT = N1 + 65536/4;       /* + 16384 */
    if (i4 >= NT) return;
    const float* src; __half* dst; int j;
    if (i4 < N0) { src = qkvw; dst = g_qkvwh; j = i4; }
    else if (i4 < N1) {
        j = i4 - N0;
        int p = j / 16384; j -= p * 16384;
        src = (p == 0 ? w2q : (p == 1 ? w2k : w2v));
        dst = g_w2h[p];
    } else { src = projw; dst = g_projh; j = i4 - N1; }
    float4 v = *(const float4*)(src + j*4);
    __half2* d = (__half2*)(dst + j*4);
    d[0] = __floats2half2_rn(v.x, v.y);
    d[1] = __floats2half2_rn(v.z, v.w);
}

/* ---------------- 4) fold BN into layer-1 affine, emit fp16 [n][k] ---------------- */
__global__ void k_fold(const float* __restrict__ qw1, const float* __restrict__ qb1,
                       const float* __restrict__ qg,  const float* __restrict__ qbe,
                       const float* __restrict__ kw1, const float* __restrict__ kb1,
                       const float* __restrict__ kg,  const float* __restrict__ kbe,
                       const float* __restrict__ vw1, const float* __restrict__ vb1,
                       const float* __restrict__ vg,  const float* __restrict__ vbe) {
    __shared__ float ws[8][PF];
    int tid = threadIdx.x;
    int wl = tid >> 5, lane = tid & 31;
    int ch = blockIdx.x * 8 + wl;
    int p = ch >> 8, c = ch & 255;
    const float* w1 = (p == 0 ? qw1 : (p == 1 ? kw1 : vw1)) + c*PF;
    const float* b1 = (p == 0 ? qb1 : (p == 1 ? kb1 : vb1));
    const float* gg = (p == 0 ? qg  : (p == 1 ? kg  : vg ));
    const float* be = (p == 0 ? qbe : (p == 1 ? kbe : vbe));
    ws[wl][lane] = w1[lane];
    if (lane < PF - 32) ws[wl][lane + 32] = w1[lane + 32];
    __syncwarp();
    float quad = 0.f, wm = 0.f;
#pragma unroll
    for (int ii = 0; ii < 2; ii++) {
        int i = lane + ii*32;
        if (i < PF) {
            float wi = ws[wl][i];
            float t = 0.f;
            for (int j = 0; j < PF; j++) t += g_S[i*PF + j] * ws[wl][j];
            quad += wi * t;
            wm   += wi * g_m[i];
        }
    }
    for (int off = 16; off > 0; off >>= 1) {
        quad += __shfl_xor_sync(0xffffffffu, quad, off);
        wm   += __shfl_xor_sync(0xffffffffu, wm,   off);
    }
    float var   = quad * (1.f / (float)NROWS) - wm * wm;
    float scale = gg[c] * rsqrtf(var + EPSC);
    float mu    = wm + b1[c];
    float b1e   = (b1[c] - mu) * scale + be[c];
#pragma unroll
    for (int ii = 0; ii < 2; ii++) {
        int j = lane + ii*32;
        if (j < PF) g_w1h[p][c*PF + j] = __float2half(ws[wl][j] * scale);
    }
    if (lane == 0) g_b1e[p][c] = b1e;
}

/* ---------------- 5) pos MLPs via fp16 mma ---------------- */
__global__ void __launch_bounds__(512, 1) k_posmlp(const float* __restrict__ pr,
        const float* __restrict__ qb2, const float* __restrict__ kb2,
        const float* __restrict__ vb2) {
    extern __shared__ __half smh[];
    __half* prs = smh;                        /* 128 x PSH */
    __half* hs  = smh + 128*PSH;              /* 128 x HSH */
    __half* bsm = hs + 128*HSH;               /* 18432 halves (B1 whole / B2 double buf) */
    int tid = threadIdx.x;
    int wid = tid >> 5, lane = tid & 31;
    int mg = wid >> 1, nh = wid & 1;
    int g = lane >> 2, t = lane & 3;
    int r0 = blockIdx.x * 128;
    int arow = mg*16 + g;

    for (int i = tid; i < 128*12; i += 512) {
        int row = i / 12, c4 = i % 12;
        float4 v = *(const float4*)(pr + (long)(r0 + row)*PF + c4*4);
        __half2* d = (__half2*)(prs + row*PSH + c4*4);
        d[0] = __floats2half2_rn(v.x, v.y);
        d[1] = __floats2half2_rn(v.z, v.w);
    }
    __syncthreads();

    for (int p = 0; p < 3; p++) {
        /* ---- layer 1: [128x48]@[48x256] -> relu -> hs (fp16) ---- */
        for (int i = tid; i < 256*6; i += 512) {
            int row = i / 6, c8 = i % 6;
            *(int4*)(bsm + row*B1SH + c8*8) = *(const int4*)(g_w1h[p] + row*PF + c8*8);
        }
        __syncthreads();
        const float* b1 = g_b1e[p];
        for (int nc = 0; nc < 2; nc++) {
            float acc[8][4];
#pragma unroll
            for (int nb = 0; nb < 8; nb++) { acc[nb][0]=acc[nb][1]=acc[nb][2]=acc[nb][3]=0.f; }
#pragma unroll
            for (int ks = 0; ks < 3; ks++) {
                uint32_t a0 = ldh2(prs + arow*PSH      + ks*16 + 2*t);
                uint32_t a1 = ldh2(prs + (arow+8)*PSH  + ks*16 + 2*t);
                uint32_t a2 = ldh2(prs + arow*PSH      + ks*16 + 8 + 2*t);
                uint32_t a3 = ldh2(prs + (arow+8)*PSH  + ks*16 + 8 + 2*t);
#pragma unroll
                for (int nb = 0; nb < 8; nb++) {
                    int cb = nc*128 + nh*64 + nb*8 + g;
                    uint32_t b0 = ldh2(bsm + cb*B1SH + ks*16 + 2*t);
                    uint32_t bv1 = ldh2(bsm + cb*B1SH + ks*16 + 8 + 2*t);
                    mma_f16(acc[nb][0], acc[nb][1], acc[nb][2], acc[nb][3],
                            a0, a1, a2, a3, b0, bv1);
                }
            }
#pragma unroll
            for (int nb = 0; nb < 8; nb++) {
                int col = nc*128 + nh*64 + nb*8 + 2*t;
                float bb0 = __ldg(&b1[col]), bb1 = __ldg(&b1[col+1]);
                *(__half2*)(hs + arow*HSH + col) =
                    __floats2half2_rn(fmaxf(acc[nb][0]+bb0, 0.f), fmaxf(acc[nb][1]+bb1, 0.f));
                *(__half2*)(hs + (arow+8)*HSH + col) =
                    __floats2half2_rn(fmaxf(acc[nb][2]+bb0, 0.f), fmaxf(acc[nb][3]+bb1, 0.f));
            }
        }
        __syncthreads();
        /* ---- layer 2: [128x256]@[256x256] + b2 -> g_posh[p] ---- */
        const float* b2 = (p == 0 ? qb2 : (p == 1 ? kb2 : vb2));
        for (int nc = 0; nc < 2; nc++) {
            float acc[8][4];
#pragma unroll
            for (int nb = 0; nb < 8; nb++) { acc[nb][0]=acc[nb][1]=acc[nb][2]=acc[nb][3]=0.f; }
            for (int kc = 0; kc < 4; kc++) {
                if (kc == 0) {
                    for (int i = tid; i < 128*8; i += 512) {
                        int row = i >> 3, c8 = i & 7;
                        *(int4*)(bsm + row*B2SH + c8*8) =
                            *(const int4*)(g_w2h[p] + (nc*128 + row)*256 + c8*8);
                    }
                    __syncthreads();
                }
                __half* bcur = bsm + (kc & 1)*128*B2SH;
                if (kc < 3) {
                    __half* bnxt = bsm + ((kc + 1) & 1)*128*B2SH;
                    for (int i = tid; i < 128*8; i += 512) {
                        int row = i >> 3, c8 = i & 7;
                        *(int4*)(bnxt + row*B2SH + c8*8) =
                            *(const int4*)(g_w2h[p] + (nc*128 + row)*256 + (kc+1)*64 + c8*8);
                    }
                }
#pragma unroll
                for (int kk = 0; kk < 4; kk++) {
                    uint32_t a0 = ldh2(hs + arow*HSH     + kc*64 + kk*16 + 2*t);
                    uint32_t a1 = ldh2(hs + (arow+8)*HSH + kc*64 + kk*16 + 2*t);
                    uint32_t a2 = ldh2(hs + arow*HSH     + kc*64 + kk*16 + 8 + 2*t);
                    uint32_t a3 = ldh2(hs + (arow+8)*HSH + kc*64 + kk*16 + 8 + 2*t);
#pragma unroll
                    for (int nb = 0; nb < 8; nb++) {
                        int cb = nh*64 + nb*8 + g;
                        uint32_t b0 = ldh2(bcur + cb*B2SH + kk*16 + 2*t);
                        uint32_t bv1 = ldh2(bcur + cb*B2SH + kk*16 + 8 + 2*t);
                        mma_f16(acc[nb][0], acc[nb][1], acc[nb][2], acc[nb][3],
                                a0, a1, a2, a3, b0, bv1);
                    }
                }
                __syncthreads();
            }
#pragma unroll
            for (int nb = 0; nb < 8; nb++) {
                int col = nc*128 + nh*64 + nb*8 + 2*t;
                float bb0 = __ldg(&b2[col]), bb1 = __ldg(&b2[col+1]);
                long gr = r0 + arow;
                *(__half2*)(&g_posh[p][gr*256 + col]) =
                    __floats2half2_rn(acc[nb][0]+bb0, acc[nb][1]+bb1);
                *(__half2*)(&g_posh[p][(gr+8)*256 + col]) =
                    __floats2half2_rn(acc[nb][2]+bb0, acc[nb][3]+bb1);
            }
        }
    }
}

/* ---------------- 6) qkv GEMM via fp16 mma -> g_qkvh ---------------- */
__global__ void __launch_bounds__(512, 1) k_qkv(const float* __restrict__ x) {
    extern __shared__ __half smh[];
    __half* xs  = smh;                       /* 128 x HSH */
    __half* bsm = smh + 128*HSH;             /* 2 x 128 x B2SH */
    int tid = threadIdx.x;
    int wid = tid >> 5, lane = tid & 31;
    int mg = wid >> 1, nh = wid & 1;
    int g = lane >> 2, t = lane & 3;
    int r0 = blockIdx.x * 128;
    int arow = mg*16 + g;

    for (int i = tid; i < 128*64; i += 512) {
        int row = i >> 6, c4 = i & 63;
        float4 v = *(const float4*)(x + (long)(r0 + row)*DIM + c4*4);
        __half2* d = (__half2*)(xs + row*HSH + c4*4);
        d[0] = __floats2half2_rn(v.x, v.y);
        d[1] = __floats2half2_rn(v.z, v.w);
    }
    __syncthreads();

    for (int nc = 0; nc < 6; nc++) {
        float acc[8][4];
#pragma unroll
        for (int nb = 0; nb < 8; nb++) { acc[nb][0]=acc[nb][1]=acc[nb][2]=acc[nb][3]=0.f; }
        for (int kc = 0; kc < 4; kc++) {
            if (kc == 0) {
                for (int i = tid; i < 128*8; i += 512) {
                    int row = i >> 3, c8 = i & 7;
                    *(int4*)(bsm + row*B2SH + c8*8) =
                        *(const int4*)(g_qkvwh + (nc*128 + row)*256 + c8*8);
                }
                __syncthreads();
            }
            __half* bcur = bsm + (kc & 1)*128*B2SH;
            if (kc < 3) {
                __half* bnxt = bsm + ((kc + 1) & 1)*128*B2SH;
                for (int i = tid; i < 128*8; i += 512) {
                    int row = i >> 3, c8 = i & 7;
                    *(int4*)(bnxt + row*B2SH + c8*8) =
                        *(const int4*)(g_qkvwh + (nc*128 + row)*256 + (kc+1)*64 + c8*8);
                }
            }
#pragma unroll
            for (int kk = 0; kk < 4; kk++) {
                uint32_t a0 = ldh2(xs + arow*HSH     + kc*64 + kk*16 + 2*t);
                uint32_t a1 = ldh2(xs + (arow+8)*HSH + kc*64 + kk*16 + 2*t);
                uint32_t a2 = ldh2(xs + arow*HSH     + kc*64 + kk*16 + 8 + 2*t);
                uint32_t a3 = ldh2(xs + (arow+8)*HSH + kc*64 + kk*16 + 8 + 2*t);
#pragma unroll
                for (int nb = 0; nb < 8; nb++) {
                    int cb = nh*64 + nb*8 + g;
                    uint32_t b0 = ldh2(bcur + cb*B2SH + kk*16 + 2*t);
                    uint32_t bv1 = ldh2(bcur + cb*B2SH + kk*16 + 8 + 2*t);
                    mma_f16(acc[nb][0], acc[nb][1], acc[nb][2], acc[nb][3],
                            a0, a1, a2, a3, b0, bv1);
                }
            }
            __syncthreads();
        }
#pragma unroll
        for (int nb = 0; nb < 8; nb++) {
            int col = nc*128 + nh*64 + nb*8 + 2*t;
            long gr = r0 + arow;
            *(__half2*)(&g_qkvh[gr*768 + col])     = __floats2half2_rn(acc[nb][0], acc[nb][1]);
            *(__half2*)(&g_qkvh[(gr+8)*768 + col]) = __floats2half2_rn(acc[nb][2], acc[nb][3]);
        }
    }
}

/* ---------------- 7) attention (fp32) + proj (fp16 mma), fused ---------------- */
__global__ void __launch_bounds__(256, 1) k_attnproj(const float* __restrict__ projb,
                                                     float* __restrict__ out) {
    extern __shared__ __half smh[];
    __half* xs  = smh;                        /* 128 x HSH fp16 attn out */
    __half* bsm = smh + 128*HSH;              /* 2 x 128 x B2SH */
    float*  wb  = (float*)(bsm + 2*128*B2SH); /* 8 warps x 2080 fp32 */
    int tid = threadIdx.x;
    int w = tid >> 5, lane = tid & 31;
    float* kk = wb + w*2080;
    float* pk = kk + 512;
    float* qb = pk + 512;
    float* kn = qb + 528;
    float* at = qb;
    long row0 = (long)blockIdx.x*128 + w*16;
    int n = lane & 15, mgh = lane >> 4;

    for (int h = 0; h < 8; h++) {
        int ho = h*32;
        for (int i2 = lane; i2 < 256; i2 += 32) {
            int m = i2 >> 4, d2 = (i2 & 15) * 2;
            float2 kr = __half22float2(*(const __half2*)(&g_qkvh[(row0+m)*768 + 256 + ho + d2]));
            float2 pq = __half22float2(*(const __half2*)(&g_posh[0][(row0+m)*256 + ho + d2]));
            float2 pkv= __half22float2(*(const __half2*)(&g_posh[1][(row0+m)*256 + ho + d2]));
            float2 qv = __half22float2(*(const __half2*)(&g_qkvh[(row0+m)*768 + ho + d2]));
            kk[m*32 + d2] = kr.x + pq.x; kk[m*32 + d2 + 1] = kr.y + pq.y;
            pk[m*32 + d2] = pkv.x;       pk[m*32 + d2 + 1] = pkv.y;
            kn[m*33 + d2] = kr.x;        kn[m*33 + d2 + 1] = kr.y;
            qb[m*33 + d2] = qv.x;        qb[m*33 + d2 + 1] = qv.y;
        }
        __syncwarp();
        float dd[8];
#pragma unroll
        for (int i = 0; i < 8; i++) dd[i] = 0.f;
        for (int d = 0; d < 32; d++) {
            float qv = qb[n*33 + d];
            float kv = kn[n*33 + d];
#pragma unroll
            for (int mm = 0; mm < 8; mm++) {
                int m = mgh*8 + mm;
                dd[mm] += qv * kk[m*32 + d] + kv * pk[m*32 + d];
            }
        }
        float mx = dd[0];
#pragma unroll
        for (int mm = 1; mm < 8; mm++) mx = fmaxf(mx, dd[mm]);
        mx = fmaxf(mx, __shfl_xor_sync(0xffffffffu, mx, 16));
        float e[8], ssum = 0.f;
#pragma unroll
        for (int mm = 0; mm < 8; mm++) { e[mm] = __expf((dd[mm] - mx) * ATT_SCALE); ssum += e[mm]; }
        ssum += __shfl_xor_sync(0xffffffffu, ssum, 16);
        float inv = 1.f / ssum;
        __syncwarp();
#pragma unroll
        for (int mm = 0; mm < 8; mm++) at[n*17 + mgh*8 + mm] = e[mm] * inv;
        __syncwarp();
        for (int i2 = lane; i2 < 256; i2 += 32) {
            int m = i2 >> 4, d2 = (i2 & 15) * 2;
            float2 vv = __half22float2(*(const __half2*)(&g_qkvh[(row0+m)*768 + 512 + ho + d2]));
            float2 pv = __half22float2(*(const __half2*)(&g_posh[2][(row0+m)*256 + ho + d2]));
            kk[m*32 + d2] = vv.x + pv.x; kk[m*32 + d2 + 1] = vv.y + pv.y;
        }
        __syncwarp();
        float o[16];
#pragma unroll
        for (int i = 0; i < 16; i++) o[i] = 0.f;
        for (int m = 0; m < 16; m++) {
            float a = at[n*17 + m];
#pragma unroll
            for (int i = 0; i < 16; i++) o[i] += a * kk[m*32 + mgh*16 + i];
        }
#pragma unroll
        for (int i2 = 0; i2 < 8; i2++)
            *(__half2*)(xs + (w*16 + n)*HSH + ho + mgh*16 + 2*i2) =
                __floats2half2_rn(o[2*i2], o[2*i2 + 1]);
        __syncwarp();
    }
    __syncthreads();

    /* proj: [128x256]@[256x256] + proj_b, fp16 mma */
    int g = lane >> 2, t = lane & 3;
    int arow = w*16 + g;
    for (int nc = 0; nc < 2; nc++) {
        float acc[16][4];
#pragma unroll
        for (int nb = 0; nb < 16; nb++) { acc[nb][0]=acc[nb][1]=acc[nb][2]=acc[nb][3]=0.f; }
        for (int kc = 0; kc < 4; kc++) {
            if (kc == 0) {
                for (int i = tid; i < 128*8; i += 256) {
                    int row = i >> 3, c8 = i & 7;
                    *(int4*)(bsm + row*B2SH + c8*8) =
                        *(const int4*)(g_projh + (nc*128 + row)*256 + c8*8);
                }
                __syncthreads();
            }
            __half* bcur = bsm + (kc & 1)*128*B2SH;
            if (kc < 3) {
                __half* bnxt = bsm + ((kc + 1) & 1)*128*B2SH;
                for (int i = tid; i < 128*8; i += 256) {
                    int row = i >> 3, c8 = i & 7;
                    *(int4*)(bnxt + row*B2SH + c8*8) =
                        *(const int4*)(g_projh + (nc*128 + row)*256 + (kc+1)*64 + c8*8);
                }
            }
#pragma unroll
            for (int kk2 = 0; kk2 < 4; kk2++) {
                uint32_t a0 = ldh2(xs + arow*HSH     + kc*64 + kk2*16 + 2*t);
                uint32_t a1 = ldh2(xs + (arow+8)*HSH + kc*64 + kk2*16 + 2*t);
                uint32_t a2 = ldh2(xs + arow*HSH     + kc*64 + kk2*16 + 8 + 2*t);
                uint32_t a3 = ldh2(xs + (arow+8)*HSH + kc*64 + kk2*16 + 8 + 2*t);
#pragma unroll
                for (int nb = 0; nb < 16; nb++) {
                    int cb = nb*8 + g;
                    uint32_t b0 = ldh2(bcur + cb*B2SH + kk2*16 + 2*t);
                    uint32_t bv1 = ldh2(bcur + cb*B2SH + kk2*16 + 8 + 2*t);
                    mma_f16(acc[nb][0], acc[nb][1], acc[nb][2], acc[nb][3],
                            a0, a1, a2, a3, b0, bv1);
                }
            }
            __syncthreads();
        }
#pragma unroll
        for (int nb = 0; nb < 16; nb++) {
            int col = nc*128 + nb*8 + 2*t;
            float bb0 = __ldg(&projb[col]), bb1 = __ldg(&projb[col+1]);
            long gr = (long)blockIdx.x*128 + arow;
            *(float2*)(&out[gr*DIM + col])     = make_float2(acc[nb][0]+bb0, acc[nb][1]+bb1);
            *(float2*)(&out[(gr+8)*DIM + col]) = make_float2(acc[nb][2]+bb0, acc[nb][3]+bb1);
        }
    }
}

/* ---------------- launcher ---------------- */
extern "C" void kernel_launch(void* const* d_in, const int* in_sizes, int n_in,
                              void* d_out, int out_size) {
    (void)in_sizes; (void)n_in; (void)out_size;
    const float* x     = (const float*)d_in[0];
    const float* pr    = (const float*)d_in[1];
    const float* qkvw  = (const float*)d_in[2];
    const float* projw = (const float*)d_in[3];
    const float* projb = (const float*)d_in[4];
    const float* qw1 = (const float*)d_in[5];
    const float* qb1 = (const float*)d_in[6];
    const float* qg  = (const float*)d_in[7];
    const float* qbe = (const float*)d_in[8];
    const float* qw2 = (const float*)d_in[9];
    const float* qb2 = (const float*)d_in[10];
    const float* kw1 = (const float*)d_in[11];
    const float* kb1 = (const float*)d_in[12];
    const float* kg  = (const float*)d_in[13];
    const float* kbe = (const float*)d_in[14];
    const float* kw2 = (const float*)d_in[15];
    const float* kb2 = (const float*)d_in[16];
    const float* vw1 = (const float*)d_in[17];
    const float* vb1 = (const float*)d_in[18];
    const float* vg  = (const float*)d_in[19];
    const float* vbe = (const float*)d_in[20];
    const float* vw2 = (const float*)d_in[21];
    const float* vb2 = (const float*)d_in[22];

    const int smem_posmlp = (128*PSH + 128*HSH + 2*128*B2SH) * 2;     /* 118784 B */
    const int smem_qkv    = (128*HSH + 2*128*B2SH) * 2;               /* 104448 B */
    const int smem_ap     = (128*HSH + 2*128*B2SH) * 2 + 8*2080*4;    /* 171008 B */
    cudaFuncSetAttribute(k_posmlp,   cudaFuncAttributeMaxDynamicSharedMemorySize, smem_posmlp);
    cudaFuncSetAttribute(k_qkv,      cudaFuncAttributeMaxDynamicSharedMemorySize, smem_qkv);
    cudaFuncSetAttribute(k_attnproj, cudaFuncAttributeMaxDynamicSharedMemorySize, smem_ap);

    k_stats_part<<<256, 256>>>(pr);
    k_stats_red<<<10, 256>>>();
    k_prep<<<224, 512>>>(qkvw, qw2, kw2, vw2, projw);
    k_fold<<<96, 256>>>(qw1, qb1, qg, qbe, kw1, kb1, kg, kbe, vw1, vb1, vg, vbe);
    k_posmlp<<<NROWS/128, 512, smem_posmlp>>>(pr, qb2, kb2, vb2);
    k_qkv<<<NROWS/128, 512, smem_qkv>>>(x);
    k_attnproj<<<NROWS/128, 256, smem_ap>>>(projb, (float*)d_out);
}

// round 6
// speedup vs baseline: 5.3804x; 1.1974x over previous
#include <cuda_runtime.h>
#include <cuda_fp16.h>
#include <stdint.h>
#include <math.h>

#define NBATCH 8192
#define NS 16
#define DIM 256
#define PF 48
#define NROWS (NBATCH*NS)   /* 131072 */
#define EPSC 1e-5f
#define ATT_SCALE 0.17677669529663687f
#define PSH 56    /* prs stride (halves) */
#define HSH 264   /* 256-col fp16 A tile stride (halves) */
#define B1SH 56   /* layer1 B stride (halves) */
#define B2SH 72   /* 64-k-chunk B stride (halves) */
#define ASH 40    /* attention per-head 16x32 tile stride (halves) */

/* ---------------- device scratch ---------------- */
__device__ float g_part_S[256][PF*PF];
__device__ float g_part_m[256][PF];
__device__ float g_S[PF*PF];
__device__ float g_m[PF];
__device__ __half g_w1h[3][256*PF];
__device__ float  g_b1e[3][DIM];
__device__ __half g_qkvwh[768*256];
__device__ __half g_w2h[3][256*256];
__device__ __half g_projh[256*256];
__device__ __half g_posh[3][(long)NROWS*256];
__device__ __half g_qkvh[(long)NROWS*768];

__device__ __forceinline__ void mma_f16(float& c0, float& c1, float& c2, float& c3,
                                        uint32_t a0, uint32_t a1, uint32_t a2, uint32_t a3,
                                        uint32_t b0, uint32_t b1) {
    asm volatile("mma.sync.aligned.m16n8k16.row.col.f32.f16.f16.f32 "
                 "{%0,%1,%2,%3},{%4,%5,%6,%7},{%8,%9},{%0,%1,%2,%3};"
                 : "+f"(c0), "+f"(c1), "+f"(c2), "+f"(c3)
                 : "r"(a0), "r"(a1), "r"(a2), "r"(a3), "r"(b0), "r"(b1));
}
__device__ __forceinline__ uint32_t sptr(const void* p) {
    return (uint32_t)__cvta_generic_to_shared(p);
}
__device__ __forceinline__ void ldsm4(uint32_t& r0, uint32_t& r1, uint32_t& r2, uint32_t& r3,
                                      uint32_t addr) {
    asm volatile("ldmatrix.sync.aligned.m8n8.x4.shared.b16 {%0,%1,%2,%3}, [%4];"
                 : "=r"(r0), "=r"(r1), "=r"(r2), "=r"(r3) : "r"(addr));
}
__device__ __forceinline__ void ldsm4t(uint32_t& r0, uint32_t& r1, uint32_t& r2, uint32_t& r3,
                                       uint32_t addr) {
    asm volatile("ldmatrix.sync.aligned.m8n8.x4.trans.shared.b16 {%0,%1,%2,%3}, [%4];"
                 : "=r"(r0), "=r"(r1), "=r"(r2), "=r"(r3) : "r"(addr));
}
__device__ __forceinline__ uint32_t h2_as_u32(__half2 h) {
    uint32_t u;
    __builtin_memcpy(&u, &h, 4);
    return u;
}
__device__ __forceinline__ uint32_t pack_h2(float a, float b) {
    return h2_as_u32(__floats2half2_rn(a, b));
}

/* ---------------- 1) partial stats ---------------- */
__global__ void k_stats_part(const float* __restrict__ pr) {
    __shared__ float ps[64*PF];
    int tid = threadIdx.x;
    int ti = tid >> 4, tj = tid & 15;
    float acc[9]; float asum[3];
#pragma unroll
    for (int i = 0; i < 9; i++) acc[i] = 0.f;
    asum[0] = asum[1] = asum[2] = 0.f;
    int r0 = blockIdx.x * 512;
    for (int t = 0; t < 8; t++) {
        const float* src = pr + (long)(r0 + t*64) * PF;
        for (int i = tid; i < 64*PF; i += 256) ps[i] = src[i];
        __syncthreads();
        for (int r = 0; r < 64; r++) {
            float si0 = ps[r*PF + 3*ti + 0];
            float si1 = ps[r*PF + 3*ti + 1];
            float si2 = ps[r*PF + 3*ti + 2];
            float sj0 = ps[r*PF + 3*tj + 0];
            float sj1 = ps[r*PF + 3*tj + 1];
            float sj2 = ps[r*PF + 3*tj + 2];
            acc[0] += si0*sj0; acc[1] += si0*sj1; acc[2] += si0*sj2;
            acc[3] += si1*sj0; acc[4] += si1*sj1; acc[5] += si1*sj2;
            acc[6] += si2*sj0; acc[7] += si2*sj1; acc[8] += si2*sj2;
            if (tj == 0) { asum[0] += si0; asum[1] += si1; asum[2] += si2; }
        }
        __syncthreads();
    }
#pragma unroll
    for (int a = 0; a < 3; a++)
#pragma unroll
        for (int bq = 0; bq < 3; bq++)
            g_part_S[blockIdx.x][(3*ti + a)*PF + 3*tj + bq] = acc[a*3 + bq];
    if (tj == 0) {
        g_part_m[blockIdx.x][3*ti + 0] = asum[0];
        g_part_m[blockIdx.x][3*ti + 1] = asum[1];
        g_part_m[blockIdx.x][3*ti + 2] = asum[2];
    }
}

/* ---------------- 2) final reduce ---------------- */
__global__ void k_stats_red() {
    int i = blockIdx.x * 256 + threadIdx.x;
    if (i < PF*PF) {
        float s = 0.f;
        for (int c = 0; c < 256; c++) s += g_part_S[c][i];
        g_S[i] = s;
    } else if (i < PF*PF + PF) {
        int j = i - PF*PF;
        float s = 0.f;
        for (int c = 0; c < 256; c++) s += g_part_m[c][j];
        g_m[j] = s * (1.f / (float)NROWS);
    }
}

/* ---------------- 3) fp32 -> fp16 weight convert ---------------- */
__global__ void k_prep(const float* __restrict__ qkvw, const float* __restrict__ w2q,
                       const float* __restrict__ w2k, const float* __restrict__ w2v,
                       const float* __restrict__ projw) {
    int i4 = blockIdx.x * blockDim.x + threadIdx.x;
    const int N0 = 768*256/4;
    const int N1 = N0 + 3*65536/4;
    const int NT = N1 + 65536/4;
    if (i4 >= NT) return;
    const float* src; __half* dst; int j;
    if (i4 < N0) { src = qkvw; dst = g_qkvwh; j = i4; }
    else if (i4 < N1) {
        j = i4 - N0;
        int p = j / 16384; j -= p * 16384;
        src = (p == 0 ? w2q : (p == 1 ? w2k : w2v));
        dst = g_w2h[p];
    } else { src = projw; dst = g_projh; j = i4 - N1; }
    float4 v = *(const float4*)(src + j*4);
    __half2* d = (__half2*)(dst + j*4);
    d[0] = __floats2half2_rn(v.x, v.y);
    d[1] = __floats2half2_rn(v.z, v.w);
}

/* ---------------- 4) fold BN into layer-1 affine ---------------- */
__global__ void k_fold(const float* __restrict__ qw1, const float* __restrict__ qb1,
                       const float* __restrict__ qg,  const float* __restrict__ qbe,
                       const float* __restrict__ kw1, const float* __restrict__ kb1,
                       const float* __restrict__ kg,  const float* __restrict__ kbe,
                       const float* __restrict__ vw1, const float* __restrict__ vb1,
                       const float* __restrict__ vg,  const float* __restrict__ vbe) {
    __shared__ float ws[8][PF];
    int tid = threadIdx.x;
    int wl = tid >> 5, lane = tid & 31;
    int ch = blockIdx.x * 8 + wl;
    int p = ch >> 8, c = ch & 255;
    const float* w1 = (p == 0 ? qw1 : (p == 1 ? kw1 : vw1)) + c*PF;
    const float* b1 = (p == 0 ? qb1 : (p == 1 ? kb1 : vb1));
    const float* gg = (p == 0 ? qg  : (p == 1 ? kg  : vg ));
    const float* be = (p == 0 ? qbe : (p == 1 ? kbe : vbe));
    ws[wl][lane] = w1[lane];
    if (lane < PF - 32) ws[wl][lane + 32] = w1[lane + 32];
    __syncwarp();
    float quad = 0.f, wm = 0.f;
#pragma unroll
    for (int ii = 0; ii < 2; ii++) {
        int i = lane + ii*32;
        if (i < PF) {
            float wi = ws[wl][i];
            float t = 0.f;
            for (int j = 0; j < PF; j++) t += g_S[i*PF + j] * ws[wl][j];
            quad += wi * t;
            wm   += wi * g_m[i];
        }
    }
    for (int off = 16; off > 0; off >>= 1) {
        quad += __shfl_xor_sync(0xffffffffu, quad, off);
        wm   += __shfl_xor_sync(0xffffffffu, wm,   off);
    }
    float var   = quad * (1.f / (float)NROWS) - wm * wm;
    float scale = gg[c] * rsqrtf(var + EPSC);
    float mu    = wm + b1[c];
    float b1e   = (b1[c] - mu) * scale + be[c];
#pragma unroll
    for (int ii = 0; ii < 2; ii++) {
        int j = lane + ii*32;
        if (j < PF) g_w1h[p][c*PF + j] = __float2half(ws[wl][j] * scale);
    }
    if (lane == 0) g_b1e[p][c] = b1e;
}

/* ---------------- 5) pos MLPs via fp16 mma + ldmatrix ---------------- */
__global__ void __launch_bounds__(512, 1) k_posmlp(const float* __restrict__ pr,
        const float* __restrict__ qb2, const float* __restrict__ kb2,
        const float* __restrict__ vb2) {
    extern __shared__ __half smh[];
    __half* prs = smh;                        /* 128 x PSH */
    __half* hs  = smh + 128*PSH;              /* 128 x HSH */
    __half* bsm = hs + 128*HSH;               /* 18432 halves */
    int tid = threadIdx.x;
    int wid = tid >> 5, lane = tid & 31;
    int mg = wid >> 1, nh = wid & 1;
    int g = lane >> 2, t = lane & 3;
    int r0 = blockIdx.x * 128;
    int arow = mg*16 + g;
    /* ldmatrix lane mappings */
    int a_row = mg*16 + (lane & 15);
    int a_koff = (lane & 16) ? 8 : 0;
    int b_nrow = (lane & 7) + ((lane & 16) ? 8 : 0);
    int b_koff = (lane & 8) ? 8 : 0;

    for (int i = tid; i < 128*12; i += 512) {
        int row = i / 12, c4 = i % 12;
        float4 v = *(const float4*)(pr + (long)(r0 + row)*PF + c4*4);
        __half2* d = (__half2*)(prs + row*PSH + c4*4);
        d[0] = __floats2half2_rn(v.x, v.y);
        d[1] = __floats2half2_rn(v.z, v.w);
    }
    __syncthreads();

    for (int p = 0; p < 3; p++) {
        /* ---- layer 1 ---- */
        for (int i = tid; i < 256*6; i += 512) {
            int row = i / 6, c8 = i % 6;
            *(int4*)(bsm + row*B1SH + c8*8) = *(const int4*)(g_w1h[p] + row*PF + c8*8);
        }
        __syncthreads();
        const float* b1 = g_b1e[p];
        for (int nc = 0; nc < 2; nc++) {
            float acc[8][4];
#pragma unroll
            for (int nb = 0; nb < 8; nb++) { acc[nb][0]=acc[nb][1]=acc[nb][2]=acc[nb][3]=0.f; }
#pragma unroll
            for (int ks = 0; ks < 3; ks++) {
                uint32_t a0,a1,a2,a3;
                ldsm4(a0,a1,a2,a3, sptr(prs + a_row*PSH + ks*16 + a_koff));
#pragma unroll
                for (int np = 0; np < 4; np++) {
                    int cb = nc*128 + nh*64 + np*16 + b_nrow;
                    uint32_t b0,b1r,b2,b3;
                    ldsm4(b0,b1r,b2,b3, sptr(bsm + cb*B1SH + ks*16 + b_koff));
                    mma_f16(acc[2*np][0],acc[2*np][1],acc[2*np][2],acc[2*np][3],
                            a0,a1,a2,a3, b0,b1r);
                    mma_f16(acc[2*np+1][0],acc[2*np+1][1],acc[2*np+1][2],acc[2*np+1][3],
                            a0,a1,a2,a3, b2,b3);
                }
            }
#pragma unroll
            for (int nb = 0; nb < 8; nb++) {
                int col = nc*128 + nh*64 + nb*8 + 2*t;
                float bb0 = __ldg(&b1[col]), bb1 = __ldg(&b1[col+1]);
                *(__half2*)(hs + arow*HSH + col) =
                    __floats2half2_rn(fmaxf(acc[nb][0]+bb0, 0.f), fmaxf(acc[nb][1]+bb1, 0.f));
                *(__half2*)(hs + (arow+8)*HSH + col) =
                    __floats2half2_rn(fmaxf(acc[nb][2]+bb0, 0.f), fmaxf(acc[nb][3]+bb1, 0.f));
            }
        }
        __syncthreads();
        /* ---- layer 2 ---- */
        const float* b2 = (p == 0 ? qb2 : (p == 1 ? kb2 : vb2));
        for (int nc = 0; nc < 2; nc++) {
            float acc[8][4];
#pragma unroll
            for (int nb = 0; nb < 8; nb++) { acc[nb][0]=acc[nb][1]=acc[nb][2]=acc[nb][3]=0.f; }
            for (int kc = 0; kc < 4; kc++) {
                if (kc == 0) {
                    for (int i = tid; i < 128*8; i += 512) {
                        int row = i >> 3, c8 = i & 7;
                        *(int4*)(bsm + row*B2SH + c8*8) =
                            *(const int4*)(g_w2h[p] + (nc*128 + row)*256 + c8*8);
                    }
                    __syncthreads();
                }
                __half* bcur = bsm + (kc & 1)*128*B2SH;
                if (kc < 3) {
                    __half* bnxt = bsm + ((kc + 1) & 1)*128*B2SH;
                    for (int i = tid; i < 128*8; i += 512) {
                        int row = i >> 3, c8 = i & 7;
                        *(int4*)(bnxt + row*B2SH + c8*8) =
                            *(const int4*)(g_w2h[p] + (nc*128 + row)*256 + (kc+1)*64 + c8*8);
                    }
                }
#pragma unroll
                for (int kk = 0; kk < 4; kk++) {
                    uint32_t a0,a1,a2,a3;
                    ldsm4(a0,a1,a2,a3, sptr(hs + a_row*HSH + kc*64 + kk*16 + a_koff));
#pragma unroll
                    for (int np = 0; np < 4; np++) {
                        int cb = nh*64 + np*16 + b_nrow;
                        uint32_t b0,b1r,b2,b3;
                        ldsm4(b0,b1r,b2,b3, sptr(bcur + cb*B2SH + kk*16 + b_koff));
                        mma_f16(acc[2*np][0],acc[2*np][1],acc[2*np][2],acc[2*np][3],
                                a0,a1,a2,a3, b0,b1r);
                        mma_f16(acc[2*np+1][0],acc[2*np+1][1],acc[2*np+1][2],acc[2*np+1][3],
                                a0,a1,a2,a3, b2,b3);
                    }
                }
                __syncthreads();
            }
#pragma unroll
            for (int nb = 0; nb < 8; nb++) {
                int col = nc*128 + nh*64 + nb*8 + 2*t;
                float bb0 = __ldg(&b2[col]), bb1 = __ldg(&b2[col+1]);
                long gr = r0 + arow;
                *(__half2*)(&g_posh[p][gr*256 + col]) =
                    __floats2half2_rn(acc[nb][0]+bb0, acc[nb][1]+bb1);
                *(__half2*)(&g_posh[p][(gr+8)*256 + col]) =
                    __floats2half2_rn(acc[nb][2]+bb0, acc[nb][3]+bb1);
            }
        }
    }
}

/* ---------------- 6) qkv GEMM via fp16 mma + ldmatrix ---------------- */
__global__ void __launch_bounds__(512, 1) k_qkv(const float* __restrict__ x) {
    extern __shared__ __half smh[];
    __half* xs  = smh;                       /* 128 x HSH */
    __half* bsm = smh + 128*HSH;             /* 2 x 128 x B2SH */
    int tid = threadIdx.x;
    int wid = tid >> 5, lane = tid & 31;
    int mg = wid >> 1, nh = wid & 1;
    int g = lane >> 2, t = lane & 3;
    int r0 = blockIdx.x * 128;
    int arow = mg*16 + g;
    int a_row = mg*16 + (lane & 15);
    int a_koff = (lane & 16) ? 8 : 0;
    int b_nrow = (lane & 7) + ((lane & 16) ? 8 : 0);
    int b_koff = (lane & 8) ? 8 : 0;

    for (int i = tid; i < 128*64; i += 512) {
        int row = i >> 6, c4 = i & 63;
        float4 v = *(const float4*)(x + (long)(r0 + row)*DIM + c4*4);
        __half2* d = (__half2*)(xs + row*HSH + c4*4);
        d[0] = __floats2half2_rn(v.x, v.y);
        d[1] = __floats2half2_rn(v.z, v.w);
    }
    __syncthreads();

    for (int nc = 0; nc < 6; nc++) {
        float acc[8][4];
#pragma unroll
        for (int nb = 0; nb < 8; nb++) { acc[nb][0]=acc[nb][1]=acc[nb][2]=acc[nb][3]=0.f; }
        for (int kc = 0; kc < 4; kc++) {
            if (kc == 0) {
                for (int i = tid; i < 128*8; i += 512) {
                    int row = i >> 3, c8 = i & 7;
                    *(int4*)(bsm + row*B2SH + c8*8) =
                        *(const int4*)(g_qkvwh + (nc*128 + row)*256 + c8*8);
                }
                __syncthreads();
            }
            __half* bcur = bsm + (kc & 1)*128*B2SH;
            if (kc < 3) {
                __half* bnxt = bsm + ((kc + 1) & 1)*128*B2SH;
                for (int i = tid; i < 128*8; i += 512) {
                    int row = i >> 3, c8 = i & 7;
                    *(int4*)(bnxt + row*B2SH + c8*8) =
                        *(const int4*)(g_qkvwh + (nc*128 + row)*256 + (kc+1)*64 + c8*8);
                }
            }
#pragma unroll
            for (int kk = 0; kk < 4; kk++) {
                uint32_t a0,a1,a2,a3;
                ldsm4(a0,a1,a2,a3, sptr(xs + a_row*HSH + kc*64 + kk*16 + a_koff));
#pragma unroll
                for (int np = 0; np < 4; np++) {
                    int cb = nh*64 + np*16 + b_nrow;
                    uint32_t b0,b1r,b2,b3;
                    ldsm4(b0,b1r,b2,b3, sptr(bcur + cb*B2SH + kk*16 + b_koff));
                    mma_f16(acc[2*np][0],acc[2*np][1],acc[2*np][2],acc[2*np][3],
                            a0,a1,a2,a3, b0,b1r);
                    mma_f16(acc[2*np+1][0],acc[2*np+1][1],acc[2*np+1][2],acc[2*np+1][3],
                            a0,a1,a2,a3, b2,b3);
                }
            }
            __syncthreads();
        }
#pragma unroll
        for (int nb = 0; nb < 8; nb++) {
            int col = nc*128 + nh*64 + nb*8 + 2*t;
            long gr = r0 + arow;
            *(__half2*)(&g_qkvh[gr*768 + col])     = __floats2half2_rn(acc[nb][0], acc[nb][1]);
            *(__half2*)(&g_qkvh[(gr+8)*768 + col]) = __floats2half2_rn(acc[nb][2], acc[nb][3]);
        }
    }
}

/* ---------------- 7) attention (tensor-core) + proj (fp16 mma), fused ---------------- */
__global__ void __launch_bounds__(256, 1) k_attnproj(const float* __restrict__ projb,
                                                     float* __restrict__ out) {
    extern __shared__ __half smh[];
    __half* xs  = smh;                        /* 128 x HSH fp16 attn out */
    __half* bsm = smh + 128*HSH;              /* 2 x 128 x B2SH */
    __half* wbh = bsm + 2*128*B2SH;           /* 8 warps x 5 x 16 x ASH */
    int tid = threadIdx.x;
    int w = tid >> 5, lane = tid & 31;
    int g = lane >> 2, t = lane & 3;
    __half* qh = wbh + w*5*16*ASH;
    __half* kh = qh + 16*ASH;
    __half* kq = kh + 16*ASH;
    __half* ph = kq + 16*ASH;
    __half* vh = ph + 16*ASH;
    long row0 = (long)blockIdx.x*128 + w*16;
    /* ldmatrix lane mappings */
    int a_row = lane & 15;
    int a_koff = (lane & 16) ? 8 : 0;
    int b_nrow = (lane & 7) + ((lane & 16) ? 8 : 0);
    int b_koff = (lane & 8) ? 8 : 0;
    int t_mrow = lane & 15;
    int t_doff = (lane & 16) ? 8 : 0;

    for (int h = 0; h < 8; h++) {
        int ho = h*32;
        for (int i2 = lane; i2 < 256; i2 += 32) {
            int m = i2 >> 4, d2 = (i2 & 15)*2;
            __half2 q2 = *(const __half2*)(&g_qkvh[(row0+m)*768 + ho + d2]);
            __half2 k2 = *(const __half2*)(&g_qkvh[(row0+m)*768 + 256 + ho + d2]);
            __half2 v2 = *(const __half2*)(&g_qkvh[(row0+m)*768 + 512 + ho + d2]);
            __half2 pq2 = *(const __half2*)(&g_posh[0][(row0+m)*256 + ho + d2]);
            __half2 pk2 = *(const __half2*)(&g_posh[1][(row0+m)*256 + ho + d2]);
            __half2 pv2 = *(const __half2*)(&g_posh[2][(row0+m)*256 + ho + d2]);
            *(__half2*)(qh + m*ASH + d2) = q2;
            *(__half2*)(kh + m*ASH + d2) = k2;
            *(__half2*)(kq + m*ASH + d2) = __hadd2(k2, pq2);
            *(__half2*)(ph + m*ASH + d2) = pk2;
            *(__half2*)(vh + m*ASH + d2) = __hadd2(v2, pv2);
        }
        __syncwarp();
        /* dots = q @ (k+pos_q)^T + k @ pos_k^T : M=16 rows, N=16 cols, K=32 */
        float c[2][4];
        c[0][0]=c[0][1]=c[0][2]=c[0][3]=0.f;
        c[1][0]=c[1][1]=c[1][2]=c[1][3]=0.f;
#pragma unroll
        for (int ks = 0; ks < 2; ks++) {
            uint32_t a0,a1,a2,a3, b0,b1r,b2,b3;
            ldsm4(a0,a1,a2,a3, sptr(qh + a_row*ASH + ks*16 + a_koff));
            ldsm4(b0,b1r,b2,b3, sptr(kq + b_nrow*ASH + ks*16 + b_koff));
            mma_f16(c[0][0],c[0][1],c[0][2],c[0][3], a0,a1,a2,a3, b0,b1r);
            mma_f16(c[1][0],c[1][1],c[1][2],c[1][3], a0,a1,a2,a3, b2,b3);
            ldsm4(a0,a1,a2,a3, sptr(kh + a_row*ASH + ks*16 + a_koff));
            ldsm4(b0,b1r,b2,b3, sptr(ph + b_nrow*ASH + ks*16 + b_koff));
            mma_f16(c[0][0],c[0][1],c[0][2],c[0][3], a0,a1,a2,a3, b0,b1r);
            mma_f16(c[1][0],c[1][1],c[1][2],c[1][3], a0,a1,a2,a3, b2,b3);
        }
        /* softmax over 16 cols; rows g (c[j][0..1]) and g+8 (c[j][2..3]) */
        float mx0 = fmaxf(fmaxf(c[0][0], c[0][1]), fmaxf(c[1][0], c[1][1]));
        float mx1 = fmaxf(fmaxf(c[0][2], c[0][3]), fmaxf(c[1][2], c[1][3]));
        mx0 = fmaxf(mx0, __shfl_xor_sync(0xffffffffu, mx0, 1));
        mx0 = fmaxf(mx0, __shfl_xor_sync(0xffffffffu, mx0, 2));
        mx1 = fmaxf(mx1, __shfl_xor_sync(0xffffffffu, mx1, 1));
        mx1 = fmaxf(mx1, __shfl_xor_sync(0xffffffffu, mx1, 2));
        float e[2][4];
#pragma unroll
        for (int j = 0; j < 2; j++) {
            e[j][0] = __expf((c[j][0] - mx0) * ATT_SCALE);
            e[j][1] = __expf((c[j][1] - mx0) * ATT_SCALE);
            e[j][2] = __expf((c[j][2] - mx1) * ATT_SCALE);
            e[j][3] = __expf((c[j][3] - mx1) * ATT_SCALE);
        }
        float s0 = e[0][0] + e[0][1] + e[1][0] + e[1][1];
        float s1 = e[0][2] + e[0][3] + e[1][2] + e[1][3];
        s0 += __shfl_xor_sync(0xffffffffu, s0, 1);
        s0 += __shfl_xor_sync(0xffffffffu, s0, 2);
        s1 += __shfl_xor_sync(0xffffffffu, s1, 1);
        s1 += __shfl_xor_sync(0xffffffffu, s1, 2);
        float inv0 = 1.f / s0, inv1 = 1.f / s1;
        /* attn fragments in-register: a-frag layout == c-frag layout */
        uint32_t pa0 = pack_h2(e[0][0]*inv0, e[0][1]*inv0);
        uint32_t pa1 = pack_h2(e[0][2]*inv1, e[0][3]*inv1);
        uint32_t pa2 = pack_h2(e[1][0]*inv0, e[1][1]*inv0);
        uint32_t pa3 = pack_h2(e[1][2]*inv1, e[1][3]*inv1);
        /* out = attn @ vv : M=16 rows, N=32 d, K=16 m ; vv^T via ldmatrix.trans */
        float o[4][4];
#pragma unroll
        for (int j = 0; j < 4; j++) { o[j][0]=o[j][1]=o[j][2]=o[j][3]=0.f; }
        {
            uint32_t b0,b1r,b2,b3;
            ldsm4t(b0,b1r,b2,b3, sptr(vh + t_mrow*ASH + t_doff));
            mma_f16(o[0][0],o[0][1],o[0][2],o[0][3], pa0,pa1,pa2,pa3, b0,b1r);
            mma_f16(o[1][0],o[1][1],o[1][2],o[1][3], pa0,pa1,pa2,pa3, b2,b3);
            ldsm4t(b0,b1r,b2,b3, sptr(vh + t_mrow*ASH + 16 + t_doff));
            mma_f16(o[2][0],o[2][1],o[2][2],o[2][3], pa0,pa1,pa2,pa3, b0,b1r);
            mma_f16(o[3][0],o[3][1],o[3][2],o[3][3], pa0,pa1,pa2,pa3, b2,b3);
        }
#pragma unroll
        for (int j = 0; j < 4; j++) {
            int col = ho + j*8 + 2*t;
            *(__half2*)(xs + (w*16 + g)*HSH + col)     = __floats2half2_rn(o[j][0], o[j][1]);
            *(__half2*)(xs + (w*16 + g + 8)*HSH + col) = __floats2half2_rn(o[j][2], o[j][3]);
        }
        __syncwarp();
    }
    __syncthreads();

    /* proj: [128x256]@[256x256] + proj_b, fp16 mma + ldmatrix */
    int a_row2 = w*16 + (lane & 15);
    int arow = w*16 + g;
    for (int nc = 0; nc < 2; nc++) {
        float acc[16][4];
#pragma unroll
        for (int nb = 0; nb < 16; nb++) { acc[nb][0]=acc[nb][1]=acc[nb][2]=acc[nb][3]=0.f; }
        for (int kc = 0; kc < 4; kc++) {
            if (kc == 0) {
                for (int i = tid; i < 128*8; i += 256) {
                    int row = i >> 3, c8 = i & 7;
                    *(int4*)(bsm + row*B2SH + c8*8) =
                        *(const int4*)(g_projh + (nc*128 + row)*256 + c8*8);
                }
                __syncthreads();
            }
            __half* bcur = bsm + (kc & 1)*128*B2SH;
            if (kc < 3) {
                __half* bnxt = bsm + ((kc + 1) & 1)*128*B2SH;
                for (int i = tid; i < 128*8; i += 256) {
                    int row = i >> 3, c8 = i & 7;
                    *(int4*)(bnxt + row*B2SH + c8*8) =
                        *(const int4*)(g_projh + (nc*128 + row)*256 + (kc+1)*64 + c8*8);
                }
            }
#pragma unroll
            for (int kk2 = 0; kk2 < 4; kk2++) {
                uint32_t a0,a1,a2,a3;
                ldsm4(a0,a1,a2,a3, sptr(xs + a_row2*HSH + kc*64 + kk2*16 + a_koff));
#pragma unroll
                for (int np = 0; np < 8; np++) {
                    int cb = np*16 + b_nrow;
                    uint32_t b0,b1r,b2,b3;
                    ldsm4(b0,b1r,b2,b3, sptr(bcur + cb*B2SH + kk2*16 + b_koff));
                    mma_f16(acc[2*np][0],acc[2*np][1],acc[2*np][2],acc[2*np][3],
                            a0,a1,a2,a3, b0,b1r);
                    mma_f16(acc[2*np+1][0],acc[2*np+1][1],acc[2*np+1][2],acc[2*np+1][3],
                            a0,a1,a2,a3, b2,b3);
                }
            }
            __syncthreads();
        }
#pragma unroll
        for (int nb = 0; nb < 16; nb++) {
            int col = nc*128 + nb*8 + 2*t;
            float bb0 = __ldg(&projb[col]), bb1 = __ldg(&projb[col+1]);
            long gr = (long)blockIdx.x*128 + arow;
            *(float2*)(&out[gr*DIM + col])     = make_float2(acc[nb][0]+bb0, acc[nb][1]+bb1);
            *(float2*)(&out[(gr+8)*DIM + col]) = make_float2(acc[nb][2]+bb0, acc[nb][3]+bb1);
        }
    }
}

/* ---------------- launcher ---------------- */
extern "C" void kernel_launch(void* const* d_in, const int* in_sizes, int n_in,
                              void* d_out, int out_size) {
    (void)in_sizes; (void)n_in; (void)out_size;
    const float* x     = (const float*)d_in[0];
    const float* pr    = (const float*)d_in[1];
    const float* qkvw  = (const float*)d_in[2];
    const float* projw = (const float*)d_in[3];
    const float* projb = (const float*)d_in[4];
    const float* qw1 = (const float*)d_in[5];
    const float* qb1 = (const float*)d_in[6];
    const float* qg  = (const float*)d_in[7];
    const float* qbe = (const float*)d_in[8];
    const float* qw2 = (const float*)d_in[9];
    const float* qb2 = (const float*)d_in[10];
    const float* kw1 = (const float*)d_in[11];
    const float* kb1 = (const float*)d_in[12];
    const float* kg  = (const float*)d_in[13];
    const float* kbe = (const float*)d_in[14];
    const float* kw2 = (const float*)d_in[15];
    const float* kb2 = (const float*)d_in[16];
    const float* vw1 = (const float*)d_in[17];
    const float* vb1 = (const float*)d_in[18];
    const float* vg  = (const float*)d_in[19];
    const float* vbe = (const float*)d_in[20];
    const float* vw2 = (const float*)d_in[21];
    const float* vb2 = (const float*)d_in[22];

    const int smem_posmlp = (128*PSH + 128*HSH + 2*128*B2SH) * 2;       /* 118784 B */
    const int smem_qkv    = (128*HSH + 2*128*B2SH) * 2;                 /* 104448 B */
    const int smem_ap     = (128*HSH + 2*128*B2SH + 8*5*16*ASH) * 2;    /* 155648 B */
    cudaFuncSetAttribute(k_posmlp,   cudaFuncAttributeMaxDynamicSharedMemorySize, smem_posmlp);
    cudaFuncSetAttribute(k_qkv,      cudaFuncAttributeMaxDynamicSharedMemorySize, smem_qkv);
    cudaFuncSetAttribute(k_attnproj, cudaFuncAttributeMaxDynamicSharedMemorySize, smem_ap);

    k_stats_part<<<256, 256>>>(pr);
    k_stats_red<<<10, 256>>>();
    k_prep<<<224, 512>>>(qkvw, qw2, kw2, vw2, projw);
    k_fold<<<96, 256>>>(qw1, qb1, qg, qbe, kw1, kb1, kg, kbe, vw1, vb1, vg, vbe);
    k_posmlp<<<NROWS/128, 512, smem_posmlp>>>(pr, qb2, kb2, vb2);
    k_qkv<<<NROWS/128, 512, smem_qkv>>>(x);
    k_attnproj<<<NROWS/128, 256, smem_ap>>>(projb, (float*)d_out);
}